// round 6
// baseline (speedup 1.0000x reference)
#include <cuda_runtime.h>
#include <cuda_bf16.h>
#include <cstdint>

#define BATCH 4096
#define NN 17
#define DIM 512
#define OUTC 3
#define KP 1536   // packed K = [hi|lo|hi] x 512

// ----------------------------- device scratch ------------------------------
__device__ __align__(16) __nv_bfloat16 g_Ap[(size_t)BATCH * KP];  // [Ahi|Alo|Ahi]
__device__ __align__(16) __nv_bfloat16 g_Bp[(size_t)DIM * KP];    // [Bhi|Bhi|Blo] (B^T rows)
__device__ __align__(16) float g_scale[(size_t)BATCH * DIM];
__device__ float g_P1T[9 * DIM];
__device__ float g_C3[9];
__device__ float g_T3[(size_t)BATCH * 9];
__device__ float g_L[NN * NN];
__device__ float g_Q[NN * NN];

__device__ __forceinline__ float silu_f(float v) { return v / (1.f + __expf(-v)); }

__device__ __forceinline__ uint32_t smem_u32(const void* p) {
    uint32_t a;
    asm("{ .reg .u64 t; cvta.to.shared.u64 t, %1; cvt.u32.u64 %0, t; }" : "=r"(a) : "l"(p));
    return a;
}
__device__ __forceinline__ void cp16(uint32_t dst, const void* src) {
    asm volatile("cp.async.cg.shared.global [%0], [%1], 16;" :: "r"(dst), "l"(src));
}
#define CP_COMMIT() asm volatile("cp.async.commit_group;" ::: "memory")
#define CP_WAIT(n)  asm volatile("cp.async.wait_group %0;" :: "n"(n) : "memory")

__device__ __forceinline__ void ldmx4(uint32_t* r, uint32_t addr) {
    asm volatile("ldmatrix.sync.aligned.m8n8.x4.shared.b16 {%0,%1,%2,%3}, [%4];"
                 : "=r"(r[0]), "=r"(r[1]), "=r"(r[2]), "=r"(r[3]) : "r"(addr));
}
__device__ __forceinline__ void mma_bf16(float* c, const uint32_t* a, const uint32_t* b) {
    asm volatile(
        "mma.sync.aligned.m16n8k16.row.col.f32.bf16.bf16.f32 "
        "{%0,%1,%2,%3}, {%4,%5,%6,%7}, {%8,%9}, {%0,%1,%2,%3};"
        : "+f"(c[0]), "+f"(c[1]), "+f"(c[2]), "+f"(c[3])
        : "r"(a[0]), "r"(a[1]), "r"(a[2]), "r"(a[3]), "r"(b[0]), "r"(b[1]));
}

// ---------------------------------------------------------------------------
// setup: blocks 0..64 compute P1^T (+C3); block 65 computes L and Q
// ---------------------------------------------------------------------------
__global__ __launch_bounds__(256) void setup_kernel(const float* __restrict__ Wmod,
                                                    const float* __restrict__ bmod,
                                                    const float* __restrict__ Wg,
                                                    const float* __restrict__ adj) {
    const int tid = threadIdx.x;
    if (blockIdx.x == 65) {
        __shared__ float sD[NN];
        __shared__ float sL[NN * NN];
        if (tid < NN) {
            float s = 0.f;
            #pragma unroll
            for (int m = 0; m < NN; m++) s += adj[tid * NN + m];
            sD[tid] = rsqrtf(s);
        }
        __syncthreads();
        for (int i = tid; i < NN * NN; i += 256) {
            int n = i / NN, m = i % NN;
            float v = ((n == m) ? 1.f : 0.f) - sD[n] * adj[i] * sD[m];
            sL[i] = v; g_L[i] = v;
        }
        __syncthreads();
        for (int i = tid; i < NN * NN; i += 256) {
            int n = i / NN, m = i % NN;
            float s = 0.f;
            #pragma unroll
            for (int j = 0; j < NN; j++) s += sL[n * NN + j] * sL[j * NN + m];
            g_Q[i] = 2.f * s - ((n == m) ? 1.f : 0.f);
        }
        return;
    }
    __shared__ float sWgT[9][DIM];
    const int w = tid >> 5, l = tid & 31;
    for (int i = tid; i < 9 * DIM; i += 256) {
        int k = i / (DIM * 3), r = i % (DIM * 3), c = r / 3, o = r % 3;
        sWgT[k * 3 + o][c] = Wg[i];
    }
    __syncthreads();
    int d = blockIdx.x * 8 + w;
    if (d > DIM) return;
    float acc[9];
    #pragma unroll
    for (int t = 0; t < 9; t++) acc[t] = 0.f;
    #pragma unroll
    for (int j = 0; j < 4; j++) {
        int idx = j * 32 + l;
        float4 wv = (d < DIM)
            ? reinterpret_cast<const float4*>(Wmod + (size_t)d * 2 * DIM)[idx]
            : reinterpret_cast<const float4*>(bmod)[idx];
        #pragma unroll
        for (int t = 0; t < 9; t++) {
            float4 p = reinterpret_cast<const float4*>(sWgT[t])[idx];
            acc[t] += wv.x * p.x + wv.y * p.y + wv.z * p.z + wv.w * p.w;
        }
    }
    #pragma unroll
    for (int t = 0; t < 9; t++) {
        float a = acc[t];
        #pragma unroll
        for (int off = 16; off; off >>= 1) a += __shfl_xor_sync(0xffffffffu, a, off);
        if (l == 0) {
            if (d < DIM) g_P1T[t * DIM + d] = a;
            else         g_C3[t] = a;
        }
    }
}

// ---------------------------------------------------------------------------
// prep_c: fused silu(c) -> bf16 hi/lo packed A' write  +  t3 dot products
// ---------------------------------------------------------------------------
__global__ __launch_bounds__(256) void prep_c(const float* __restrict__ cin) {
    __shared__ float sP[9][DIM];
    __shared__ float sC[9];
    const int tid = threadIdx.x, w = tid >> 5, l = tid & 31;
    for (int i = tid; i < 9 * DIM; i += 256) (&sP[0][0])[i] = g_P1T[i];
    if (tid < 9) sC[tid] = g_C3[tid];
    __syncthreads();
    const int b = blockIdx.x * 8 + w;
    float acc[9];
    #pragma unroll
    for (int t = 0; t < 9; t++) acc[t] = 0.f;
    const float4* cv = reinterpret_cast<const float4*>(cin + (size_t)b * DIM);
    __nv_bfloat16* ap = g_Ap + (size_t)b * KP;
    #pragma unroll
    for (int j = 0; j < 4; j++) {
        int idx = j * 32 + l;
        float4 v = cv[idx];
        float s[4] = { silu_f(v.x), silu_f(v.y), silu_f(v.z), silu_f(v.w) };
        union U { __nv_bfloat16 b[4]; uint2 u; } hi, lo;
        #pragma unroll
        for (int e = 0; e < 4; e++) {
            __nv_bfloat16 h = __float2bfloat16(s[e]);
            hi.b[e] = h;
            lo.b[e] = __float2bfloat16(s[e] - __bfloat162float(h));
        }
        int kb = idx * 4;
        *reinterpret_cast<uint2*>(ap + kb)        = hi.u;
        *reinterpret_cast<uint2*>(ap + 512 + kb)  = lo.u;
        *reinterpret_cast<uint2*>(ap + 1024 + kb) = hi.u;
        #pragma unroll
        for (int t = 0; t < 9; t++) {
            float4 p = reinterpret_cast<const float4*>(sP[t])[idx];
            acc[t] += s[0] * p.x + s[1] * p.y + s[2] * p.z + s[3] * p.w;
        }
    }
    #pragma unroll
    for (int t = 0; t < 9; t++) {
        float a = acc[t];
        #pragma unroll
        for (int off = 16; off; off >>= 1) a += __shfl_xor_sync(0xffffffffu, a, off);
        if (l == 0) g_T3[(size_t)b * 9 + t] = a + sC[t];
    }
}

// ---------------------------------------------------------------------------
// prep_w2t: B'[n][*] from W_mod[k, 512+n] (tiled transpose + hi/lo split)
// ---------------------------------------------------------------------------
__global__ void prep_w2t(const float* __restrict__ Wmod) {
    __shared__ float tile[32][33];
    int tx = threadIdx.x, ty = threadIdx.y;
    int n0 = blockIdx.x * 32, k0 = blockIdx.y * 32;
    tile[ty][tx] = Wmod[(size_t)(k0 + ty) * (2 * DIM) + DIM + n0 + tx];
    __syncthreads();
    float v = tile[tx][ty];
    __nv_bfloat16 h = __float2bfloat16(v);
    __nv_bfloat16 lo = __float2bfloat16(v - __bfloat162float(h));
    size_t base = (size_t)(n0 + ty) * KP + (k0 + tx);
    g_Bp[base]        = h;
    g_Bp[base + 512]  = h;
    g_Bp[base + 1024] = lo;
}

// ---------------------------------------------------------------------------
// scale GEMM: [4096,512] = A'[4096,1536] @ B'^T
// CTA 128x64, 3-stage cp.async, 2 CTAs/SM (grid 256 = 1 wave on 128 SMs)
// ---------------------------------------------------------------------------
#define TM 128
#define TN 64
#define TK 64
#define NSTAGE 3
#define A_ST_B (TM * TK * 2)              // 16384
#define B_ST_B (TN * TK * 2)              // 8192
#define STAGE_B (A_ST_B + B_ST_B)         // 24576
#define GSMEM (STAGE_B * NSTAGE)          // 73728

__global__ __launch_bounds__(256, 2) void scale_gemm(const float* __restrict__ bmod) {
    extern __shared__ __align__(128) char sm[];
    const uint32_t sbase = smem_u32(sm);
    const int tid = threadIdx.x;
    const int wid = tid >> 5, l = tid & 31;
    const int wm = wid >> 1, wn = wid & 1;          // warp tile 32x32
    const int m0 = blockIdx.x * TM, n0 = blockIdx.y * TN;

    auto load_stage = [&](int st, int chunk) {
        uint32_t abase = sbase + st * STAGE_B;
        uint32_t bbase = abase + A_ST_B;
        int k0 = chunk * TK;
        #pragma unroll
        for (int i = 0; i < 4; i++) {                       // A: 1024 16B chunks
            int id = tid + i * 256;
            int row = id >> 3, kc = id & 7;
            uint32_t dst = abase + row * 128 + ((kc ^ (row & 7)) << 4);
            cp16(dst, g_Ap + (size_t)(m0 + row) * KP + k0 + kc * 8);
        }
        #pragma unroll
        for (int i = 0; i < 2; i++) {                       // B: 512 16B chunks
            int id = tid + i * 256;
            int row = id >> 3, kc = id & 7;
            uint32_t dst = bbase + row * 128 + ((kc ^ (row & 7)) << 4);
            cp16(dst, g_Bp + (size_t)(n0 + row) * KP + k0 + kc * 8);
        }
    };

    float acc[2][4][4];
    #pragma unroll
    for (int mt = 0; mt < 2; mt++)
        #pragma unroll
        for (int nt = 0; nt < 4; nt++)
            #pragma unroll
            for (int e = 0; e < 4; e++) acc[mt][nt][e] = 0.f;

    load_stage(0, 0); CP_COMMIT();
    load_stage(1, 1); CP_COMMIT();

    const int NCHUNK = KP / TK;            // 24
    for (int it = 0; it < NCHUNK; ++it) {
        CP_WAIT(1);
        __syncthreads();
        if (it + 2 < NCHUNK) {
            int st = (it + 2) % 3;
            load_stage(st, it + 2);
        }
        CP_COMMIT();
        uint32_t abase = sbase + (it % 3) * STAGE_B;
        uint32_t bbase = abase + A_ST_B;
        #pragma unroll
        for (int kk = 0; kk < 4; kk++) {                    // k16 steps
            int kc0 = kk * 2 + (l >> 4);
            uint32_t a[2][4], b[2][4];
            #pragma unroll
            for (int mt = 0; mt < 2; mt++) {
                int row = wm * 32 + mt * 16 + (l & 15);
                ldmx4(a[mt], abase + row * 128 + ((kc0 ^ (row & 7)) << 4));
            }
            #pragma unroll
            for (int g = 0; g < 2; g++) {
                int row = wn * 32 + g * 16 + (l & 15);
                ldmx4(b[g], bbase + row * 128 + ((kc0 ^ (row & 7)) << 4));
            }
            #pragma unroll
            for (int mt = 0; mt < 2; mt++)
                #pragma unroll
                for (int g = 0; g < 2; g++) {
                    uint32_t b0[2] = { b[g][0], b[g][2] };
                    uint32_t b1[2] = { b[g][1], b[g][3] };
                    mma_bf16(acc[mt][2 * g],     a[mt], b0);
                    mma_bf16(acc[mt][2 * g + 1], a[mt], b1);
                }
        }
    }
    CP_WAIT(0);

    const int fr = l >> 2, fc = (l & 3) * 2;
    #pragma unroll
    for (int mt = 0; mt < 2; mt++) {
        int m = m0 + wm * 32 + mt * 16 + fr;
        #pragma unroll
        for (int nt = 0; nt < 4; nt++) {
            int n = n0 + wn * 32 + nt * 8 + fc;
            float2 bv = *reinterpret_cast<const float2*>(bmod + DIM + n);
            float2 v0 = make_float2(acc[mt][nt][0] + bv.x, acc[mt][nt][1] + bv.y);
            float2 v1 = make_float2(acc[mt][nt][2] + bv.x, acc[mt][nt][3] + bv.y);
            *reinterpret_cast<float2*>(g_scale + (size_t)m * DIM + n) = v0;
            *reinterpret_cast<float2*>(g_scale + (size_t)(m + 8) * DIM + n) = v1;
        }
    }
}

// ---------------------------------------------------------------------------
// final: single-pass LN+project via ws trick.
//   ws[t][c] = (1+scale_c)*Wg[t][c];  u[t] = sum_c ws[t][c]
//   dot[n][t] = x[n] . ws[t];   y[n][t] = rstd_n*(dot - mu_n*u[t])
//   out = y0 + L(y1+t3_1) + Q(y2+t3_2) + t3_0 + bg
// 1 batch/block, 17 warps (1 row each), 544 threads.
// ---------------------------------------------------------------------------
__global__ __launch_bounds__(544) void final_kernel(const float* __restrict__ x,
                                                    const float* __restrict__ Wg,
                                                    const float* __restrict__ bg,
                                                    float* __restrict__ out) {
    __shared__ float sWs[9][DIM];
    __shared__ float sS[DIM];
    __shared__ float sL[NN * NN];
    __shared__ float sQ[NN * NN];
    __shared__ float sU[9];
    __shared__ float sDot[NN][9];
    __shared__ float sMu[NN], sR[NN];
    __shared__ float sT3[9];
    __shared__ float sY[3][NN][OUTC];

    const int b = blockIdx.x;
    const int tid = threadIdx.x;
    const int w = tid >> 5;
    const int l = tid & 31;

    for (int i = tid; i < DIM / 4; i += 544)
        reinterpret_cast<float4*>(sS)[i] =
            reinterpret_cast<const float4*>(g_scale + (size_t)b * DIM)[i];
    for (int i = tid; i < NN * NN; i += 544) { sL[i] = g_L[i]; sQ[i] = g_Q[i]; }
    if (tid < 9) sT3[tid] = g_T3[(size_t)b * 9 + tid];
    __syncthreads();

    for (int i = tid; i < 9 * DIM; i += 544) {
        int k = i / (DIM * 3), r = i % (DIM * 3), c = r / 3, o = r % 3;
        sWs[k * 3 + o][c] = Wg[i] * (1.f + sS[c]);
    }
    __syncthreads();

    // u[t] by warps 0..8
    if (w < 9) {
        float u = 0.f;
        #pragma unroll
        for (int j = 0; j < 4; j++) {
            float4 v = reinterpret_cast<const float4*>(sWs[w])[j * 32 + l];
            u += (v.x + v.y) + (v.z + v.w);
        }
        #pragma unroll
        for (int off = 16; off; off >>= 1) u += __shfl_xor_sync(0xffffffffu, u, off);
        if (l == 0) sU[w] = u;
    }

    // row pass: warp w handles row w (single pass: stats + 9 raw-x dots)
    {
        float s = 0.f, s2 = 0.f, d[9];
        #pragma unroll
        for (int t = 0; t < 9; t++) d[t] = 0.f;
        const float4* xp = reinterpret_cast<const float4*>(x + ((size_t)b * NN + w) * DIM);
        #pragma unroll
        for (int j = 0; j < 4; j++) {
            float4 v = xp[j * 32 + l];
            s  += (v.x + v.y) + (v.z + v.w);
            s2 += (v.x * v.x + v.y * v.y) + (v.z * v.z + v.w * v.w);
            #pragma unroll
            for (int t = 0; t < 9; t++) {
                float4 wv = reinterpret_cast<const float4*>(sWs[t])[j * 32 + l];
                d[t] += v.x * wv.x + v.y * wv.y + v.z * wv.z + v.w * wv.w;
            }
        }
        #pragma unroll
        for (int off = 16; off; off >>= 1) {
            s  += __shfl_xor_sync(0xffffffffu, s,  off);
            s2 += __shfl_xor_sync(0xffffffffu, s2, off);
            #pragma unroll
            for (int t = 0; t < 9; t++)
                d[t] += __shfl_xor_sync(0xffffffffu, d[t], off);
        }
        if (l == 0) {
            float mu = s * (1.f / DIM);
            float var = s2 * (1.f / DIM) - mu * mu;
            sMu[w] = mu;
            sR[w]  = rsqrtf(var + 1e-6f);
            #pragma unroll
            for (int t = 0; t < 9; t++) sDot[w][t] = d[t];
        }
    }
    __syncthreads();

    if (tid < 3 * NN * OUTC) {                 // 153 threads
        int k = tid / (NN * OUTC), r = tid % (NN * OUTC);
        int n = r / OUTC, o = r % OUTC;
        int t = k * 3 + o;
        sY[k][n][o] = sR[n] * (sDot[n][t] - sMu[n] * sU[t]);
    }
    __syncthreads();

    if (tid < NN * OUTC) {
        int n = tid / OUTC, o = tid - n * OUTC;
        float t31 = sT3[3 + o], t32 = sT3[6 + o];
        float res = sY[0][n][o] + sT3[o] + bg[o];
        #pragma unroll
        for (int m = 0; m < NN; m++)
            res += sL[n * NN + m] * (sY[1][m][o] + t31)
                 + sQ[n * NN + m] * (sY[2][m][o] + t32);
        out[((size_t)b * NN + n) * OUTC + o] = res;
    }
}

// ---------------------------------------------------------------------------
extern "C" void kernel_launch(void* const* d_in, const int* in_sizes, int n_in,
                              void* d_out, int out_size) {
    const float* x     = (const float*)d_in[0];  // [4096,17,512]
    const float* adj   = (const float*)d_in[1];  // [17,17]
    const float* c     = (const float*)d_in[2];  // [4096,1,512]
    const float* W_mod = (const float*)d_in[3];  // [512,1024]
    const float* b_mod = (const float*)d_in[4];  // [1024]
    const float* Wg    = (const float*)d_in[5];  // [3,512,3]
    const float* bg    = (const float*)d_in[6];  // [3]
    float* out = (float*)d_out;                  // [4096,17,3] f32

    cudaFuncSetAttribute(scale_gemm, cudaFuncAttributeMaxDynamicSharedMemorySize, GSMEM);

    setup_kernel<<<66, 256>>>(W_mod, b_mod, Wg, adj);
    prep_w2t<<<dim3(16, 16), dim3(32, 32)>>>(W_mod);
    prep_c<<<BATCH / 8, 256>>>(c);
    scale_gemm<<<dim3(BATCH / TM, DIM / TN), 256, GSMEM>>>(b_mod);
    final_kernel<<<BATCH, 544>>>(x, Wg, bg, out);
}

// round 7
// speedup vs baseline: 1.2733x; 1.2733x over previous
#include <cuda_runtime.h>
#include <cuda_bf16.h>
#include <cstdint>

#define BATCH 4096
#define NN 17
#define DIM 512
#define OUTC 3
#define KP 1536   // packed K = [hi|lo|hi] x 512

// ----------------------------- device scratch ------------------------------
__device__ __align__(16) __nv_bfloat16 g_Ap[(size_t)BATCH * KP];  // [Ahi|Alo|Ahi]
__device__ __align__(16) __nv_bfloat16 g_Bp[(size_t)DIM * KP];    // [Bhi|Bhi|Blo] (B^T rows)
__device__ __align__(16) float g_scale[(size_t)BATCH * DIM];
__device__ float g_P1T[9 * DIM];
__device__ float g_C3[9];
__device__ float g_T3[(size_t)BATCH * 9];
__device__ float g_L[NN * NN];
__device__ float g_Q[NN * NN];

__device__ __forceinline__ float silu_f(float v) { return v / (1.f + __expf(-v)); }

__device__ __forceinline__ uint32_t smem_u32(const void* p) {
    uint32_t a;
    asm("{ .reg .u64 t; cvta.to.shared.u64 t, %1; cvt.u32.u64 %0, t; }" : "=r"(a) : "l"(p));
    return a;
}
__device__ __forceinline__ void cp16(uint32_t dst, const void* src) {
    asm volatile("cp.async.cg.shared.global [%0], [%1], 16;" :: "r"(dst), "l"(src));
}
#define CP_COMMIT() asm volatile("cp.async.commit_group;" ::: "memory")
#define CP_WAIT(n)  asm volatile("cp.async.wait_group %0;" :: "n"(n) : "memory")

__device__ __forceinline__ void ldmx4(uint32_t* r, uint32_t addr) {
    asm volatile("ldmatrix.sync.aligned.m8n8.x4.shared.b16 {%0,%1,%2,%3}, [%4];"
                 : "=r"(r[0]), "=r"(r[1]), "=r"(r[2]), "=r"(r[3]) : "r"(addr));
}
__device__ __forceinline__ void mma_bf16(float* c, const uint32_t* a, const uint32_t* b) {
    asm volatile(
        "mma.sync.aligned.m16n8k16.row.col.f32.bf16.bf16.f32 "
        "{%0,%1,%2,%3}, {%4,%5,%6,%7}, {%8,%9}, {%0,%1,%2,%3};"
        : "+f"(c[0]), "+f"(c[1]), "+f"(c[2]), "+f"(c[3])
        : "r"(a[0]), "r"(a[1]), "r"(a[2]), "r"(a[3]), "r"(b[0]), "r"(b[1]));
}

// -------- packed f32x2 (PTX ISA 8.6, sm_100+ baseline; NOT arch-'a' gated) --
typedef unsigned long long u64;
union F2 { float2 f; u64 u; };
__device__ __forceinline__ u64 pack2(float a, float b) {
    F2 t; t.f = make_float2(a, b); return t.u;
}
#define FMA2(acc, a, b) asm("fma.rn.f32x2 %0, %1, %2, %0;" : "+l"(acc) : "l"(a), "l"(b))
#define MUL2(d, a, b)   asm("mul.rn.f32x2 %0, %1, %2;"     : "=l"(d)  : "l"(a), "l"(b))
#define ADD2(d, a, b)   asm("add.rn.f32x2 %0, %1, %2;"     : "=l"(d)  : "l"(a), "l"(b))

// ---------------------------------------------------------------------------
// setup: blocks 0..64 compute P1^T (+C3); block 65 computes L and Q
// ---------------------------------------------------------------------------
__global__ __launch_bounds__(256) void setup_kernel(const float* __restrict__ Wmod,
                                                    const float* __restrict__ bmod,
                                                    const float* __restrict__ Wg,
                                                    const float* __restrict__ adj) {
    const int tid = threadIdx.x;
    if (blockIdx.x == 65) {
        __shared__ float sD[NN];
        __shared__ float sL[NN * NN];
        if (tid < NN) {
            float s = 0.f;
            #pragma unroll
            for (int m = 0; m < NN; m++) s += adj[tid * NN + m];
            sD[tid] = rsqrtf(s);
        }
        __syncthreads();
        for (int i = tid; i < NN * NN; i += 256) {
            int n = i / NN, m = i % NN;
            float v = ((n == m) ? 1.f : 0.f) - sD[n] * adj[i] * sD[m];
            sL[i] = v; g_L[i] = v;
        }
        __syncthreads();
        for (int i = tid; i < NN * NN; i += 256) {
            int n = i / NN, m = i % NN;
            float s = 0.f;
            #pragma unroll
            for (int j = 0; j < NN; j++) s += sL[n * NN + j] * sL[j * NN + m];
            g_Q[i] = 2.f * s - ((n == m) ? 1.f : 0.f);
        }
        return;
    }
    __shared__ float sWgT[9][DIM];
    const int w = tid >> 5, l = tid & 31;
    for (int i = tid; i < 9 * DIM; i += 256) {
        int k = i / (DIM * 3), r = i % (DIM * 3), c = r / 3, o = r % 3;
        sWgT[k * 3 + o][c] = Wg[i];
    }
    __syncthreads();
    int d = blockIdx.x * 8 + w;
    if (d > DIM) return;
    float acc[9];
    #pragma unroll
    for (int t = 0; t < 9; t++) acc[t] = 0.f;
    #pragma unroll
    for (int j = 0; j < 4; j++) {
        int idx = j * 32 + l;
        float4 wv = (d < DIM)
            ? reinterpret_cast<const float4*>(Wmod + (size_t)d * 2 * DIM)[idx]
            : reinterpret_cast<const float4*>(bmod)[idx];
        #pragma unroll
        for (int t = 0; t < 9; t++) {
            float4 p = reinterpret_cast<const float4*>(sWgT[t])[idx];
            acc[t] += wv.x * p.x + wv.y * p.y + wv.z * p.z + wv.w * p.w;
        }
    }
    #pragma unroll
    for (int t = 0; t < 9; t++) {
        float a = acc[t];
        #pragma unroll
        for (int off = 16; off; off >>= 1) a += __shfl_xor_sync(0xffffffffu, a, off);
        if (l == 0) {
            if (d < DIM) g_P1T[t * DIM + d] = a;
            else         g_C3[t] = a;
        }
    }
}

// ---------------------------------------------------------------------------
// prep_c: fused silu(c) -> bf16 hi/lo packed A' write  +  t3 dot products
// ---------------------------------------------------------------------------
__global__ __launch_bounds__(256) void prep_c(const float* __restrict__ cin) {
    __shared__ float sP[9][DIM];
    __shared__ float sC[9];
    const int tid = threadIdx.x, w = tid >> 5, l = tid & 31;
    for (int i = tid; i < 9 * DIM; i += 256) (&sP[0][0])[i] = g_P1T[i];
    if (tid < 9) sC[tid] = g_C3[tid];
    __syncthreads();
    const int b = blockIdx.x * 8 + w;
    float acc[9];
    #pragma unroll
    for (int t = 0; t < 9; t++) acc[t] = 0.f;
    const float4* cv = reinterpret_cast<const float4*>(cin + (size_t)b * DIM);
    __nv_bfloat16* ap = g_Ap + (size_t)b * KP;
    #pragma unroll
    for (int j = 0; j < 4; j++) {
        int idx = j * 32 + l;
        float4 v = cv[idx];
        float s[4] = { silu_f(v.x), silu_f(v.y), silu_f(v.z), silu_f(v.w) };
        union U { __nv_bfloat16 b[4]; uint2 u; } hi, lo;
        #pragma unroll
        for (int e = 0; e < 4; e++) {
            __nv_bfloat16 h = __float2bfloat16(s[e]);
            hi.b[e] = h;
            lo.b[e] = __float2bfloat16(s[e] - __bfloat162float(h));
        }
        int kb = idx * 4;
        *reinterpret_cast<uint2*>(ap + kb)        = hi.u;
        *reinterpret_cast<uint2*>(ap + 512 + kb)  = lo.u;
        *reinterpret_cast<uint2*>(ap + 1024 + kb) = hi.u;
        #pragma unroll
        for (int t = 0; t < 9; t++) {
            float4 p = reinterpret_cast<const float4*>(sP[t])[idx];
            acc[t] += s[0] * p.x + s[1] * p.y + s[2] * p.z + s[3] * p.w;
        }
    }
    #pragma unroll
    for (int t = 0; t < 9; t++) {
        float a = acc[t];
        #pragma unroll
        for (int off = 16; off; off >>= 1) a += __shfl_xor_sync(0xffffffffu, a, off);
        if (l == 0) g_T3[(size_t)b * 9 + t] = a + sC[t];
    }
}

// ---------------------------------------------------------------------------
// prep_w2t: B'[n][*] from W_mod[k, 512+n] (tiled transpose + hi/lo split)
// ---------------------------------------------------------------------------
__global__ void prep_w2t(const float* __restrict__ Wmod) {
    __shared__ float tile[32][33];
    int tx = threadIdx.x, ty = threadIdx.y;
    int n0 = blockIdx.x * 32, k0 = blockIdx.y * 32;
    tile[ty][tx] = Wmod[(size_t)(k0 + ty) * (2 * DIM) + DIM + n0 + tx];
    __syncthreads();
    float v = tile[tx][ty];
    __nv_bfloat16 h = __float2bfloat16(v);
    __nv_bfloat16 lo = __float2bfloat16(v - __bfloat162float(h));
    size_t base = (size_t)(n0 + ty) * KP + (k0 + tx);
    g_Bp[base]        = h;
    g_Bp[base + 512]  = h;
    g_Bp[base + 1024] = lo;
}

// ---------------------------------------------------------------------------
// scale GEMM (R4 config — 26.6us measured): [4096,512] = A'[4096,1536] @ B'^T
// CTA 128x128, 4-stage cp.async + ldmatrix + XOR swizzle, 8 warps (4m x 2n)
// ---------------------------------------------------------------------------
#define TM 128
#define TN 128
#define TK 64
#define NSTAGE 4
#define A_ST_B (TM * TK * 2)              // 16384 bytes
#define B_ST_B (TN * TK * 2)              // 16384 bytes
#define STAGE_B (A_ST_B + B_ST_B)         // 32768
#define GSMEM (STAGE_B * NSTAGE)          // 131072

__global__ __launch_bounds__(256, 1) void scale_gemm(const float* __restrict__ bmod) {
    extern __shared__ __align__(128) char sm[];
    const uint32_t sbase = smem_u32(sm);
    const int tid = threadIdx.x;
    const int wid = tid >> 5, l = tid & 31;
    const int wm = wid >> 1, wn = wid & 1;
    const int m0 = blockIdx.x * TM, n0 = blockIdx.y * TN;

    auto load_stage = [&](int st, int chunk) {
        uint32_t abase = sbase + st * STAGE_B;
        uint32_t bbase = abase + A_ST_B;
        int k0 = chunk * TK;
        #pragma unroll
        for (int i = 0; i < 4; i++) {                       // A: 1024 16B-chunks
            int id = tid + i * 256;
            int row = id >> 3, kc = id & 7;
            uint32_t dst = abase + row * 128 + ((kc ^ (row & 7)) << 4);
            cp16(dst, g_Ap + (size_t)(m0 + row) * KP + k0 + kc * 8);
        }
        #pragma unroll
        for (int i = 0; i < 4; i++) {                       // B: 1024 16B-chunks
            int id = tid + i * 256;
            int row = id >> 3, kc = id & 7;
            uint32_t dst = bbase + row * 128 + ((kc ^ (row & 7)) << 4);
            cp16(dst, g_Bp + (size_t)(n0 + row) * KP + k0 + kc * 8);
        }
    };

    float acc[2][8][4];
    #pragma unroll
    for (int mt = 0; mt < 2; mt++)
        #pragma unroll
        for (int nt = 0; nt < 8; nt++)
            #pragma unroll
            for (int e = 0; e < 4; e++) acc[mt][nt][e] = 0.f;

    #pragma unroll
    for (int s = 0; s < 3; s++) { load_stage(s, s); CP_COMMIT(); }

    const int NCHUNK = KP / TK;            // 24
    for (int it = 0; it < NCHUNK; ++it) {
        CP_WAIT(2);
        __syncthreads();
        if (it + 3 < NCHUNK) load_stage((it + 3) & 3, it + 3);
        CP_COMMIT();
        uint32_t abase = sbase + (it & 3) * STAGE_B;
        uint32_t bbase = abase + A_ST_B;
        #pragma unroll
        for (int kk = 0; kk < 4; kk++) {                    // k16 steps
            int kc0 = kk * 2 + (l >> 4);
            uint32_t a[2][4], b[4][4];
            #pragma unroll
            for (int mt = 0; mt < 2; mt++) {
                int row = wm * 32 + mt * 16 + (l & 15);
                ldmx4(a[mt], abase + row * 128 + ((kc0 ^ (row & 7)) << 4));
            }
            #pragma unroll
            for (int g = 0; g < 4; g++) {
                int row = wn * 64 + g * 16 + (l & 15);
                ldmx4(b[g], bbase + row * 128 + ((kc0 ^ (row & 7)) << 4));
            }
            #pragma unroll
            for (int mt = 0; mt < 2; mt++)
                #pragma unroll
                for (int g = 0; g < 4; g++) {
                    uint32_t b0[2] = { b[g][0], b[g][2] };
                    uint32_t b1[2] = { b[g][1], b[g][3] };
                    mma_bf16(acc[mt][2 * g],     a[mt], b0);
                    mma_bf16(acc[mt][2 * g + 1], a[mt], b1);
                }
        }
    }
    CP_WAIT(0);

    const int fr = l >> 2, fc = (l & 3) * 2;
    #pragma unroll
    for (int mt = 0; mt < 2; mt++) {
        int m = m0 + wm * 32 + mt * 16 + fr;
        #pragma unroll
        for (int nt = 0; nt < 8; nt++) {
            int n = n0 + wn * 64 + nt * 8 + fc;
            float2 bv = *reinterpret_cast<const float2*>(bmod + DIM + n);
            float2 v0 = make_float2(acc[mt][nt][0] + bv.x, acc[mt][nt][1] + bv.y);
            float2 v1 = make_float2(acc[mt][nt][2] + bv.x, acc[mt][nt][3] + bv.y);
            *reinterpret_cast<float2*>(g_scale + (size_t)m * DIM + n) = v0;
            *reinterpret_cast<float2*>(g_scale + (size_t)(m + 8) * DIM + n) = v1;
        }
    }
}

// ---------------------------------------------------------------------------
// final (R4 structure + packed f32x2 math):
// 2 b per block; 6 warps x 3 rows; sMod holds (1+scale);
// xm = (v + (-mu)) * (rstd*(1+sc)) via add/mul.f32x2, dots via fma.f32x2.
// ---------------------------------------------------------------------------
__global__ __launch_bounds__(192) void final_kernel(const float* __restrict__ x,
                                                    const float* __restrict__ Wg,
                                                    const float* __restrict__ bg,
                                                    float* __restrict__ out) {
    __shared__ float sWg[9][DIM];
    __shared__ float sMod[DIM];          // (1 + scale)
    __shared__ float sL[NN * NN];
    __shared__ float sQ[NN * NN];
    __shared__ float sY4[3][NN][OUTC][4];
    __shared__ float sYs[3][NN][OUTC];
    __shared__ float sT3[9];

    const int tid = threadIdx.x;
    const int w = tid >> 5;
    const int l = tid & 31;

    for (int i = tid; i < 9 * DIM; i += 192) {
        int k = i / (DIM * 3), r = i % (DIM * 3), c = r / 3, o = r % 3;
        sWg[k * 3 + o][c] = Wg[i];
    }
    for (int i = tid; i < NN * NN; i += 192) { sL[i] = g_L[i]; sQ[i] = g_Q[i]; }
    __syncthreads();

    for (int bb = 0; bb < 2; ++bb) {
        const int b = blockIdx.x * 2 + bb;
        if (bb) __syncthreads();
        if (tid < 128) {
            float4 s = reinterpret_cast<const float4*>(g_scale + (size_t)b * DIM)[tid];
            s.x += 1.f; s.y += 1.f; s.z += 1.f; s.w += 1.f;
            reinterpret_cast<float4*>(sMod)[tid] = s;
        }
        if (tid < 9) sT3[tid] = g_T3[(size_t)b * 9 + tid];
        __syncthreads();

        float4 xr[3][4];
        float nmu[3], rstd[3];
        #pragma unroll
        for (int r = 0; r < 3; r++) {
            int n = w * 3 + r; if (n > NN - 1) n = NN - 1;
            const float4* xp = reinterpret_cast<const float4*>(x + ((size_t)b * NN + n) * DIM);
            float s = 0.f, s2 = 0.f;
            #pragma unroll
            for (int j = 0; j < 4; j++) {
                float4 v = xp[j * 32 + l];
                xr[r][j] = v;
                s  += (v.x + v.y) + (v.z + v.w);
                s2 += (v.x * v.x + v.y * v.y) + (v.z * v.z + v.w * v.w);
            }
            #pragma unroll
            for (int off = 16; off; off >>= 1) {
                s  += __shfl_xor_sync(0xffffffffu, s,  off);
                s2 += __shfl_xor_sync(0xffffffffu, s2, off);
            }
            float mu  = s * (1.f / DIM);
            float var = s2 * (1.f / DIM) - mu * mu;
            nmu[r]  = -mu;
            rstd[r] = rsqrtf(var + 1e-6f);
        }

        u64 acc2[3][9];
        #pragma unroll
        for (int r = 0; r < 3; r++)
            #pragma unroll
            for (int t = 0; t < 9; t++) acc2[r][t] = 0ull;

        #pragma unroll
        for (int j = 0; j < 4; j++) {
            float4 sc = reinterpret_cast<const float4*>(sMod)[j * 32 + l];
            u64 sc01 = pack2(sc.x, sc.y), sc23 = pack2(sc.z, sc.w);
            u64 wv01[9], wv23[9];
            #pragma unroll
            for (int t = 0; t < 9; t++) {
                float4 wv = reinterpret_cast<const float4*>(sWg[t])[j * 32 + l];
                wv01[t] = pack2(wv.x, wv.y);
                wv23[t] = pack2(wv.z, wv.w);
            }
            #pragma unroll
            for (int r = 0; r < 3; r++) {
                u64 rst2 = pack2(rstd[r], rstd[r]);
                u64 nmu2 = pack2(nmu[r], nmu[r]);
                float4 v = xr[r][j];
                u64 v01 = pack2(v.x, v.y), v23 = pack2(v.z, v.w);
                u64 g01, g23, t01, t23, xm01, xm23;
                MUL2(g01, sc01, rst2);
                MUL2(g23, sc23, rst2);
                ADD2(t01, v01, nmu2);
                ADD2(t23, v23, nmu2);
                MUL2(xm01, t01, g01);
                MUL2(xm23, t23, g23);
                #pragma unroll
                for (int t = 0; t < 9; t++) {
                    FMA2(acc2[r][t], xm01, wv01[t]);
                    FMA2(acc2[r][t], xm23, wv23[t]);
                }
            }
        }

        // 3-step butterfly -> 4 partials per (row, t), lanes 0-3 write
        #pragma unroll
        for (int r = 0; r < 3; r++) {
            int n = w * 3 + r;
            #pragma unroll
            for (int t = 0; t < 9; t++) {
                F2 u; u.u = acc2[r][t];
                float a = u.f.x + u.f.y;
                a += __shfl_xor_sync(0xffffffffu, a, 16);
                a += __shfl_xor_sync(0xffffffffu, a, 8);
                a += __shfl_xor_sync(0xffffffffu, a, 4);
                if (l < 4 && n < NN) sY4[t / 3][n][t % 3][l] = a;
            }
        }
        __syncthreads();
        if (tid < 3 * NN * OUTC) {               // 153
            int k = tid / (NN * OUTC), r = tid % (NN * OUTC);
            int n = r / OUTC, o = r % OUTC;
            const float* p = sY4[k][n][o];
            sYs[k][n][o] = (p[0] + p[1]) + (p[2] + p[3]);
        }
        __syncthreads();

        if (tid < NN * OUTC) {
            int n = tid / OUTC, o = tid - n * OUTC;
            float t31 = sT3[3 + o], t32 = sT3[6 + o];
            float res = sYs[0][n][o] + sT3[o] + bg[o];
            #pragma unroll
            for (int m = 0; m < NN; m++)
                res += sL[n * NN + m] * (sYs[1][m][o] + t31)
                     + sQ[n * NN + m] * (sYs[2][m][o] + t32);
            out[((size_t)b * NN + n) * OUTC + o] = res;
        }
    }
}

// ---------------------------------------------------------------------------
extern "C" void kernel_launch(void* const* d_in, const int* in_sizes, int n_in,
                              void* d_out, int out_size) {
    const float* x     = (const float*)d_in[0];  // [4096,17,512]
    const float* adj   = (const float*)d_in[1];  // [17,17]
    const float* c     = (const float*)d_in[2];  // [4096,1,512]
    const float* W_mod = (const float*)d_in[3];  // [512,1024]
    const float* b_mod = (const float*)d_in[4];  // [1024]
    const float* Wg    = (const float*)d_in[5];  // [3,512,3]
    const float* bg    = (const float*)d_in[6];  // [3]
    float* out = (float*)d_out;                  // [4096,17,3] f32

    cudaFuncSetAttribute(scale_gemm, cudaFuncAttributeMaxDynamicSharedMemorySize, GSMEM);

    setup_kernel<<<66, 256>>>(W_mod, b_mod, Wg, adj);
    prep_w2t<<<dim3(16, 16), dim3(32, 32)>>>(W_mod);
    prep_c<<<BATCH / 8, 256>>>(c);
    scale_gemm<<<dim3(BATCH / TM, DIM / TN), 256, GSMEM>>>(b_mod);
    final_kernel<<<BATCH / 2, 192>>>(x, Wg, bg, out);
}

// round 9
// speedup vs baseline: 1.2737x; 1.0003x over previous
#include <cuda_runtime.h>
#include <cuda_bf16.h>
#include <cstdint>

#define BATCH 4096
#define NN 17
#define DIM 512
#define OUTC 3
#define KP 1536   // packed K = [hi|lo|hi] x 512

// ----------------------------- device scratch ------------------------------
__device__ __align__(16) __nv_bfloat16 g_Ap[(size_t)BATCH * KP];  // [Ahi|Alo|Ahi]
__device__ __align__(16) __nv_bfloat16 g_Bp[(size_t)DIM * KP];    // [Bhi|Bhi|Blo] (B^T rows)
__device__ __align__(16) float g_scale[(size_t)BATCH * DIM];
__device__ float g_P1T[9 * DIM];
__device__ float g_C3[9];
__device__ float g_T3[(size_t)BATCH * 9];
__device__ float g_L[NN * NN];
__device__ float g_Q[NN * NN];

__device__ __forceinline__ float silu_f(float v) { return v / (1.f + __expf(-v)); }

__device__ __forceinline__ uint32_t smem_u32(const void* p) {
    uint32_t a;
    asm("{ .reg .u64 t; cvta.to.shared.u64 t, %1; cvt.u32.u64 %0, t; }" : "=r"(a) : "l"(p));
    return a;
}
__device__ __forceinline__ void cp16(uint32_t dst, const void* src) {
    asm volatile("cp.async.cg.shared.global [%0], [%1], 16;" :: "r"(dst), "l"(src));
}
#define CP_COMMIT() asm volatile("cp.async.commit_group;" ::: "memory")
#define CP_WAIT(n)  asm volatile("cp.async.wait_group %0;" :: "n"(n) : "memory")

__device__ __forceinline__ void ldmx4(uint32_t* r, uint32_t addr) {
    asm volatile("ldmatrix.sync.aligned.m8n8.x4.shared.b16 {%0,%1,%2,%3}, [%4];"
                 : "=r"(r[0]), "=r"(r[1]), "=r"(r[2]), "=r"(r[3]) : "r"(addr));
}
__device__ __forceinline__ void mma_bf16(float* c, const uint32_t* a, const uint32_t* b) {
    asm volatile(
        "mma.sync.aligned.m16n8k16.row.col.f32.bf16.bf16.f32 "
        "{%0,%1,%2,%3}, {%4,%5,%6,%7}, {%8,%9}, {%0,%1,%2,%3};"
        : "+f"(c[0]), "+f"(c[1]), "+f"(c[2]), "+f"(c[3])
        : "r"(a[0]), "r"(a[1]), "r"(a[2]), "r"(a[3]), "r"(b[0]), "r"(b[1]));
}

// -------- packed f32x2 (PTX ISA 8.6, sm_100+ baseline; NOT arch-'a' gated) --
typedef unsigned long long u64;
union F2 { float2 f; u64 u; };
__device__ __forceinline__ u64 pack2(float a, float b) {
    F2 t; t.f = make_float2(a, b); return t.u;
}
#define FMA2(acc, a, b) asm("fma.rn.f32x2 %0, %1, %2, %0;" : "+l"(acc) : "l"(a), "l"(b))
#define MUL2(d, a, b)   asm("mul.rn.f32x2 %0, %1, %2;"     : "=l"(d)  : "l"(a), "l"(b))
#define ADD2(d, a, b)   asm("add.rn.f32x2 %0, %1, %2;"     : "=l"(d)  : "l"(a), "l"(b))

// ---------------------------------------------------------------------------
// setup: blocks 0..64 compute P1^T (+C3); block 65 computes L and Q
// ---------------------------------------------------------------------------
__global__ __launch_bounds__(256) void setup_kernel(const float* __restrict__ Wmod,
                                                    const float* __restrict__ bmod,
                                                    const float* __restrict__ Wg,
                                                    const float* __restrict__ adj) {
    const int tid = threadIdx.x;
    if (blockIdx.x == 65) {
        __shared__ float sD[NN];
        __shared__ float sL[NN * NN];
        if (tid < NN) {
            float s = 0.f;
            #pragma unroll
            for (int m = 0; m < NN; m++) s += adj[tid * NN + m];
            sD[tid] = rsqrtf(s);
        }
        __syncthreads();
        for (int i = tid; i < NN * NN; i += 256) {
            int n = i / NN, m = i % NN;
            float v = ((n == m) ? 1.f : 0.f) - sD[n] * adj[i] * sD[m];
            sL[i] = v; g_L[i] = v;
        }
        __syncthreads();
        for (int i = tid; i < NN * NN; i += 256) {
            int n = i / NN, m = i % NN;
            float s = 0.f;
            #pragma unroll
            for (int j = 0; j < NN; j++) s += sL[n * NN + j] * sL[j * NN + m];
            g_Q[i] = 2.f * s - ((n == m) ? 1.f : 0.f);
        }
        return;
    }
    __shared__ float sWgT[9][DIM];
    const int w = tid >> 5, l = tid & 31;
    for (int i = tid; i < 9 * DIM; i += 256) {
        int k = i / (DIM * 3), r = i % (DIM * 3), c = r / 3, o = r % 3;
        sWgT[k * 3 + o][c] = Wg[i];
    }
    __syncthreads();
    int d = blockIdx.x * 8 + w;
    if (d > DIM) return;
    float acc[9];
    #pragma unroll
    for (int t = 0; t < 9; t++) acc[t] = 0.f;
    #pragma unroll
    for (int j = 0; j < 4; j++) {
        int idx = j * 32 + l;
        float4 wv = (d < DIM)
            ? reinterpret_cast<const float4*>(Wmod + (size_t)d * 2 * DIM)[idx]
            : reinterpret_cast<const float4*>(bmod)[idx];
        #pragma unroll
        for (int t = 0; t < 9; t++) {
            float4 p = reinterpret_cast<const float4*>(sWgT[t])[idx];
            acc[t] += wv.x * p.x + wv.y * p.y + wv.z * p.z + wv.w * p.w;
        }
    }
    #pragma unroll
    for (int t = 0; t < 9; t++) {
        float a = acc[t];
        #pragma unroll
        for (int off = 16; off; off >>= 1) a += __shfl_xor_sync(0xffffffffu, a, off);
        if (l == 0) {
            if (d < DIM) g_P1T[t * DIM + d] = a;
            else         g_C3[t] = a;
        }
    }
}

// ---------------------------------------------------------------------------
// prep_c: fused silu(c) -> bf16 hi/lo packed A' write  +  t3 dot products
// ---------------------------------------------------------------------------
__global__ __launch_bounds__(256) void prep_c(const float* __restrict__ cin) {
    __shared__ float sP[9][DIM];
    __shared__ float sC[9];
    const int tid = threadIdx.x, w = tid >> 5, l = tid & 31;
    for (int i = tid; i < 9 * DIM; i += 256) (&sP[0][0])[i] = g_P1T[i];
    if (tid < 9) sC[tid] = g_C3[tid];
    __syncthreads();
    const int b = blockIdx.x * 8 + w;
    float acc[9];
    #pragma unroll
    for (int t = 0; t < 9; t++) acc[t] = 0.f;
    const float4* cv = reinterpret_cast<const float4*>(cin + (size_t)b * DIM);
    __nv_bfloat16* ap = g_Ap + (size_t)b * KP;
    #pragma unroll
    for (int j = 0; j < 4; j++) {
        int idx = j * 32 + l;
        float4 v = cv[idx];
        float s[4] = { silu_f(v.x), silu_f(v.y), silu_f(v.z), silu_f(v.w) };
        union U { __nv_bfloat16 b[4]; uint2 u; } hi, lo;
        #pragma unroll
        for (int e = 0; e < 4; e++) {
            __nv_bfloat16 h = __float2bfloat16(s[e]);
            hi.b[e] = h;
            lo.b[e] = __float2bfloat16(s[e] - __bfloat162float(h));
        }
        int kb = idx * 4;
        *reinterpret_cast<uint2*>(ap + kb)        = hi.u;
        *reinterpret_cast<uint2*>(ap + 512 + kb)  = lo.u;
        *reinterpret_cast<uint2*>(ap + 1024 + kb) = hi.u;
        #pragma unroll
        for (int t = 0; t < 9; t++) {
            float4 p = reinterpret_cast<const float4*>(sP[t])[idx];
            acc[t] += s[0] * p.x + s[1] * p.y + s[2] * p.z + s[3] * p.w;
        }
    }
    #pragma unroll
    for (int t = 0; t < 9; t++) {
        float a = acc[t];
        #pragma unroll
        for (int off = 16; off; off >>= 1) a += __shfl_xor_sync(0xffffffffu, a, off);
        if (l == 0) g_T3[(size_t)b * 9 + t] = a + sC[t];
    }
}

// ---------------------------------------------------------------------------
// prep_w2t: B'[n][*] from W_mod[k, 512+n] (tiled transpose + hi/lo split)
// ---------------------------------------------------------------------------
__global__ void prep_w2t(const float* __restrict__ Wmod) {
    __shared__ float tile[32][33];
    int tx = threadIdx.x, ty = threadIdx.y;
    int n0 = blockIdx.x * 32, k0 = blockIdx.y * 32;
    tile[ty][tx] = Wmod[(size_t)(k0 + ty) * (2 * DIM) + DIM + n0 + tx];
    __syncthreads();
    float v = tile[tx][ty];
    __nv_bfloat16 h = __float2bfloat16(v);
    __nv_bfloat16 lo = __float2bfloat16(v - __bfloat162float(h));
    size_t base = (size_t)(n0 + ty) * KP + (k0 + tx);
    g_Bp[base]        = h;
    g_Bp[base + 512]  = h;
    g_Bp[base + 1024] = lo;
}

// ---------------------------------------------------------------------------
// scale GEMM: [4096,512] = A'[4096,1536] @ B'^T
// CTA 128x128, 512 threads (16 warps, warp tile 32x32), 3-stage cp.async,
// ldmatrix + XOR swizzle. grid (32, 4) = 128 blocks.
// ---------------------------------------------------------------------------
#define TM 128
#define TN 128
#define TK 64
#define NSTAGE 3
#define A_ST_B (TM * TK * 2)              // 16384 bytes
#define B_ST_B (TN * TK * 2)              // 16384 bytes
#define STAGE_B (A_ST_B + B_ST_B)         // 32768
#define GSMEM (STAGE_B * NSTAGE)          // 98304

__global__ __launch_bounds__(512, 1) void scale_gemm(const float* __restrict__ bmod) {
    extern __shared__ __align__(128) char sm[];
    const uint32_t sbase = smem_u32(sm);
    const int tid = threadIdx.x;
    const int wid = tid >> 5, l = tid & 31;
    const int wm = wid >> 2, wn = wid & 3;          // 4m x 4n warps, 32x32 tile
    const int m0 = blockIdx.x * TM, n0 = blockIdx.y * TN;

    auto load_stage = [&](int st, int chunk) {
        uint32_t abase = sbase + st * STAGE_B;
        uint32_t bbase = abase + A_ST_B;
        int k0 = chunk * TK;
        #pragma unroll
        for (int i = 0; i < 2; i++) {                       // A: 1024 16B-chunks
            int id = tid + i * 512;
            int row = id >> 3, kc = id & 7;
            uint32_t dst = abase + row * 128 + ((kc ^ (row & 7)) << 4);
            cp16(dst, g_Ap + (size_t)(m0 + row) * KP + k0 + kc * 8);
        }
        #pragma unroll
        for (int i = 0; i < 2; i++) {                       // B: 1024 16B-chunks
            int id = tid + i * 512;
            int row = id >> 3, kc = id & 7;
            uint32_t dst = bbase + row * 128 + ((kc ^ (row & 7)) << 4);
            cp16(dst, g_Bp + (size_t)(n0 + row) * KP + k0 + kc * 8);
        }
    };

    float acc[2][4][4];
    #pragma unroll
    for (int mt = 0; mt < 2; mt++)
        #pragma unroll
        for (int nt = 0; nt < 4; nt++)
            #pragma unroll
            for (int e = 0; e < 4; e++) acc[mt][nt][e] = 0.f;

    load_stage(0, 0); CP_COMMIT();
    load_stage(1, 1); CP_COMMIT();

    const int NCHUNK = KP / TK;            // 24
    for (int it = 0; it < NCHUNK; ++it) {
        CP_WAIT(1);
        __syncthreads();
        if (it + 2 < NCHUNK) load_stage((it + 2) % 3, it + 2);
        CP_COMMIT();
        uint32_t abase = sbase + (it % 3) * STAGE_B;
        uint32_t bbase = abase + A_ST_B;
        #pragma unroll
        for (int kk = 0; kk < 4; kk++) {                    // k16 steps
            int kc0 = kk * 2 + (l >> 4);
            uint32_t a[2][4], b[2][4];
            #pragma unroll
            for (int mt = 0; mt < 2; mt++) {
                int row = wm * 32 + mt * 16 + (l & 15);
                ldmx4(a[mt], abase + row * 128 + ((kc0 ^ (row & 7)) << 4));
            }
            #pragma unroll
            for (int g = 0; g < 2; g++) {
                int row = wn * 32 + g * 16 + (l & 15);
                ldmx4(b[g], bbase + row * 128 + ((kc0 ^ (row & 7)) << 4));
            }
            #pragma unroll
            for (int mt = 0; mt < 2; mt++)
                #pragma unroll
                for (int g = 0; g < 2; g++) {
                    uint32_t b0[2] = { b[g][0], b[g][2] };
                    uint32_t b1[2] = { b[g][1], b[g][3] };
                    mma_bf16(acc[mt][2 * g],     a[mt], b0);
                    mma_bf16(acc[mt][2 * g + 1], a[mt], b1);
                }
        }
    }
    CP_WAIT(0);

    const int fr = l >> 2, fc = (l & 3) * 2;
    #pragma unroll
    for (int mt = 0; mt < 2; mt++) {
        int m = m0 + wm * 32 + mt * 16 + fr;
        #pragma unroll
        for (int nt = 0; nt < 4; nt++) {
            int n = n0 + wn * 32 + nt * 8 + fc;
            float2 bv = *reinterpret_cast<const float2*>(bmod + DIM + n);
            float2 v0 = make_float2(acc[mt][nt][0] + bv.x, acc[mt][nt][1] + bv.y);
            float2 v1 = make_float2(acc[mt][nt][2] + bv.x, acc[mt][nt][3] + bv.y);
            *reinterpret_cast<float2*>(g_scale + (size_t)m * DIM + n) = v0;
            *reinterpret_cast<float2*>(g_scale + (size_t)(m + 8) * DIM + n) = v1;
        }
    }
}

// ---------------------------------------------------------------------------
// final (R7 structure, staging amortized over 4 batches/block):
// 6 warps x 3 rows; sMod holds (1+scale);
// xm = (v + (-mu)) * (rstd*(1+sc)) via add/mul.f32x2, dots via fma.f32x2.
// ---------------------------------------------------------------------------
#define BPB 4

__global__ __launch_bounds__(192) void final_kernel(const float* __restrict__ x,
                                                    const float* __restrict__ Wg,
                                                    const float* __restrict__ bg,
                                                    float* __restrict__ out) {
    __shared__ float sWg[9][DIM];
    __shared__ float sMod[DIM];          // (1 + scale)
    __shared__ float sL[NN * NN];
    __shared__ float sQ[NN * NN];
    __shared__ float sY4[3][NN][OUTC][4];
    __shared__ float sYs[3][NN][OUTC];
    __shared__ float sT3[9];

    const int tid = threadIdx.x;
    const int w = tid >> 5;
    const int l = tid & 31;

    for (int i = tid; i < 9 * DIM; i += 192) {
        int k = i / (DIM * 3), r = i % (DIM * 3), c = r / 3, o = r % 3;
        sWg[k * 3 + o][c] = Wg[i];
    }
    for (int i = tid; i < NN * NN; i += 192) { sL[i] = g_L[i]; sQ[i] = g_Q[i]; }
    __syncthreads();

    for (int bb = 0; bb < BPB; ++bb) {
        const int b = blockIdx.x * BPB + bb;
        if (bb) __syncthreads();
        if (tid < 128) {
            float4 s = reinterpret_cast<const float4*>(g_scale + (size_t)b * DIM)[tid];
            s.x += 1.f; s.y += 1.f; s.z += 1.f; s.w += 1.f;
            reinterpret_cast<float4*>(sMod)[tid] = s;
        }
        if (tid < 9) sT3[tid] = g_T3[(size_t)b * 9 + tid];
        __syncthreads();

        float4 xr[3][4];
        float nmu[3], rstd[3];
        #pragma unroll
        for (int r = 0; r < 3; r++) {
            int n = w * 3 + r; if (n > NN - 1) n = NN - 1;
            const float4* xp = reinterpret_cast<const float4*>(x + ((size_t)b * NN + n) * DIM);
            float s = 0.f, s2 = 0.f;
            #pragma unroll
            for (int j = 0; j < 4; j++) {
                float4 v = xp[j * 32 + l];
                xr[r][j] = v;
                s  += (v.x + v.y) + (v.z + v.w);
                s2 += (v.x * v.x + v.y * v.y) + (v.z * v.z + v.w * v.w);
            }
            #pragma unroll
            for (int off = 16; off; off >>= 1) {
                s  += __shfl_xor_sync(0xffffffffu, s,  off);
                s2 += __shfl_xor_sync(0xffffffffu, s2, off);
            }
            float mu  = s * (1.f / DIM);
            float var = s2 * (1.f / DIM) - mu * mu;
            nmu[r]  = -mu;
            rstd[r] = rsqrtf(var + 1e-6f);
        }

        u64 acc2[3][9];
        #pragma unroll
        for (int r = 0; r < 3; r++)
            #pragma unroll
            for (int t = 0; t < 9; t++) acc2[r][t] = 0ull;

        #pragma unroll
        for (int j = 0; j < 4; j++) {
            float4 sc = reinterpret_cast<const float4*>(sMod)[j * 32 + l];
            u64 sc01 = pack2(sc.x, sc.y), sc23 = pack2(sc.z, sc.w);
            u64 wv01[9], wv23[9];
            #pragma unroll
            for (int t = 0; t < 9; t++) {
                float4 wv = reinterpret_cast<const float4*>(sWg[t])[j * 32 + l];
                wv01[t] = pack2(wv.x, wv.y);
                wv23[t] = pack2(wv.z, wv.w);
            }
            #pragma unroll
            for (int r = 0; r < 3; r++) {
                u64 rst2 = pack2(rstd[r], rstd[r]);
                u64 nmu2 = pack2(nmu[r], nmu[r]);
                float4 v = xr[r][j];
                u64 v01 = pack2(v.x, v.y), v23 = pack2(v.z, v.w);
                u64 g01, g23, t01, t23, xm01, xm23;
                MUL2(g01, sc01, rst2);
                MUL2(g23, sc23, rst2);
                ADD2(t01, v01, nmu2);
                ADD2(t23, v23, nmu2);
                MUL2(xm01, t01, g01);
                MUL2(xm23, t23, g23);
                #pragma unroll
                for (int t = 0; t < 9; t++) {
                    FMA2(acc2[r][t], xm01, wv01[t]);
                    FMA2(acc2[r][t], xm23, wv23[t]);
                }
            }
        }

        // 3-step butterfly -> 4 partials per (row, t), lanes 0-3 write
        #pragma unroll
        for (int r = 0; r < 3; r++) {
            int n = w * 3 + r;
            #pragma unroll
            for (int t = 0; t < 9; t++) {
                F2 u; u.u = acc2[r][t];
                float a = u.f.x + u.f.y;
                a += __shfl_xor_sync(0xffffffffu, a, 16);
                a += __shfl_xor_sync(0xffffffffu, a, 8);
                a += __shfl_xor_sync(0xffffffffu, a, 4);
                if (l < 4 && n < NN) sY4[t / 3][n][t % 3][l] = a;
            }
        }
        __syncthreads();
        if (tid < 3 * NN * OUTC) {               // 153
            int k = tid / (NN * OUTC), r = tid % (NN * OUTC);
            int n = r / OUTC, o = r % OUTC;
            const float* p = sY4[k][n][o];
            sYs[k][n][o] = (p[0] + p[1]) + (p[2] + p[3]);
        }
        __syncthreads();

        if (tid < NN * OUTC) {
            int n = tid / OUTC, o = tid - n * OUTC;
            float t31 = sT3[3 + o], t32 = sT3[6 + o];
            float res = sYs[0][n][o] + sT3[o] + bg[o];
            #pragma unroll
            for (int m = 0; m < NN; m++)
                res += sL[n * NN + m] * (sYs[1][m][o] + t31)
                     + sQ[n * NN + m] * (sYs[2][m][o] + t32);
            out[((size_t)b * NN + n) * OUTC + o] = res;
        }
    }
}

// ---------------------------------------------------------------------------
extern "C" void kernel_launch(void* const* d_in, const int* in_sizes, int n_in,
                              void* d_out, int out_size) {
    const float* x     = (const float*)d_in[0];  // [4096,17,512]
    const float* adj   = (const float*)d_in[1];  // [17,17]
    const float* c     = (const float*)d_in[2];  // [4096,1,512]
    const float* W_mod = (const float*)d_in[3];  // [512,1024]
    const float* b_mod = (const float*)d_in[4];  // [1024]
    const float* Wg    = (const float*)d_in[5];  // [3,512,3]
    const float* bg    = (const float*)d_in[6];  // [3]
    float* out = (float*)d_out;                  // [4096,17,3] f32

    cudaFuncSetAttribute(scale_gemm, cudaFuncAttributeMaxDynamicSharedMemorySize, GSMEM);

    setup_kernel<<<66, 256>>>(W_mod, b_mod, Wg, adj);
    prep_w2t<<<dim3(16, 16), dim3(32, 32)>>>(W_mod);
    prep_c<<<BATCH / 8, 256>>>(c);
    scale_gemm<<<dim3(BATCH / TM, DIM / TN), 512, GSMEM>>>(b_mod);
    final_kernel<<<BATCH / BPB, 192>>>(x, Wg, bg, out);
}

// round 10
// speedup vs baseline: 1.3532x; 1.0624x over previous
#include <cuda_runtime.h>
#include <cuda_bf16.h>
#include <cstdint>

#define BATCH 4096
#define NN 17
#define DIM 512
#define OUTC 3
#define KP 1536   // packed K = [hi|lo|hi] x 512

// ----------------------------- device scratch ------------------------------
__device__ __align__(16) __nv_bfloat16 g_Ap[(size_t)BATCH * KP];  // [Ahi|Alo|Ahi]
__device__ __align__(16) __nv_bfloat16 g_Bp[(size_t)DIM * KP];    // [Bhi|Bhi|Blo] (B^T rows)
__device__ __align__(16) float g_scale[(size_t)BATCH * DIM];
__device__ float g_P1T[9 * DIM];
__device__ float g_C3[9];
__device__ float g_T3[(size_t)BATCH * 9];
__device__ float g_L[NN * NN];
__device__ float g_Q[NN * NN];

__device__ __forceinline__ float silu_f(float v) { return v / (1.f + __expf(-v)); }

__device__ __forceinline__ uint32_t smem_u32(const void* p) {
    uint32_t a;
    asm("{ .reg .u64 t; cvta.to.shared.u64 t, %1; cvt.u32.u64 %0, t; }" : "=r"(a) : "l"(p));
    return a;
}
__device__ __forceinline__ void cp16(uint32_t dst, const void* src) {
    asm volatile("cp.async.cg.shared.global [%0], [%1], 16;" :: "r"(dst), "l"(src));
}
#define CP_COMMIT() asm volatile("cp.async.commit_group;" ::: "memory")
#define CP_WAIT(n)  asm volatile("cp.async.wait_group %0;" :: "n"(n) : "memory")

__device__ __forceinline__ void ldmx4(uint32_t* r, uint32_t addr) {
    asm volatile("ldmatrix.sync.aligned.m8n8.x4.shared.b16 {%0,%1,%2,%3}, [%4];"
                 : "=r"(r[0]), "=r"(r[1]), "=r"(r[2]), "=r"(r[3]) : "r"(addr));
}
__device__ __forceinline__ void mma_bf16(float* c, const uint32_t* a, const uint32_t* b) {
    asm volatile(
        "mma.sync.aligned.m16n8k16.row.col.f32.bf16.bf16.f32 "
        "{%0,%1,%2,%3}, {%4,%5,%6,%7}, {%8,%9}, {%0,%1,%2,%3};"
        : "+f"(c[0]), "+f"(c[1]), "+f"(c[2]), "+f"(c[3])
        : "r"(a[0]), "r"(a[1]), "r"(a[2]), "r"(a[3]), "r"(b[0]), "r"(b[1]));
}

// -------- packed f32x2 (PTX ISA 8.6, sm_100+ baseline; NOT arch-'a' gated) --
typedef unsigned long long u64;
union F2 { float2 f; u64 u; };
__device__ __forceinline__ u64 pack2(float a, float b) {
    F2 t; t.f = make_float2(a, b); return t.u;
}
#define FMA2(acc, a, b)   asm("fma.rn.f32x2 %0, %1, %2, %0;" : "+l"(acc) : "l"(a), "l"(b))
#define FMA23(d, a, b, c) asm("fma.rn.f32x2 %0, %1, %2, %3;" : "=l"(d)  : "l"(a), "l"(b), "l"(c))
#define MUL2(d, a, b)     asm("mul.rn.f32x2 %0, %1, %2;"     : "=l"(d)  : "l"(a), "l"(b))
#define ADD2(d, a, b)     asm("add.rn.f32x2 %0, %1, %2;"     : "=l"(d)  : "l"(a), "l"(b))

// ---------------------------------------------------------------------------
// setup: blocks 0..64 compute P1^T (+C3); block 65 computes L and Q
// ---------------------------------------------------------------------------
__global__ __launch_bounds__(256) void setup_kernel(const float* __restrict__ Wmod,
                                                    const float* __restrict__ bmod,
                                                    const float* __restrict__ Wg,
                                                    const float* __restrict__ adj) {
    const int tid = threadIdx.x;
    if (blockIdx.x == 65) {
        __shared__ float sD[NN];
        __shared__ float sL[NN * NN];
        if (tid < NN) {
            float s = 0.f;
            #pragma unroll
            for (int m = 0; m < NN; m++) s += adj[tid * NN + m];
            sD[tid] = rsqrtf(s);
        }
        __syncthreads();
        for (int i = tid; i < NN * NN; i += 256) {
            int n = i / NN, m = i % NN;
            float v = ((n == m) ? 1.f : 0.f) - sD[n] * adj[i] * sD[m];
            sL[i] = v; g_L[i] = v;
        }
        __syncthreads();
        for (int i = tid; i < NN * NN; i += 256) {
            int n = i / NN, m = i % NN;
            float s = 0.f;
            #pragma unroll
            for (int j = 0; j < NN; j++) s += sL[n * NN + j] * sL[j * NN + m];
            g_Q[i] = 2.f * s - ((n == m) ? 1.f : 0.f);
        }
        return;
    }
    __shared__ float sWgT[9][DIM];
    const int w = tid >> 5, l = tid & 31;
    for (int i = tid; i < 9 * DIM; i += 256) {
        int k = i / (DIM * 3), r = i % (DIM * 3), c = r / 3, o = r % 3;
        sWgT[k * 3 + o][c] = Wg[i];
    }
    __syncthreads();
    int d = blockIdx.x * 8 + w;
    if (d > DIM) return;
    float acc[9];
    #pragma unroll
    for (int t = 0; t < 9; t++) acc[t] = 0.f;
    #pragma unroll
    for (int j = 0; j < 4; j++) {
        int idx = j * 32 + l;
        float4 wv = (d < DIM)
            ? reinterpret_cast<const float4*>(Wmod + (size_t)d * 2 * DIM)[idx]
            : reinterpret_cast<const float4*>(bmod)[idx];
        #pragma unroll
        for (int t = 0; t < 9; t++) {
            float4 p = reinterpret_cast<const float4*>(sWgT[t])[idx];
            acc[t] += wv.x * p.x + wv.y * p.y + wv.z * p.z + wv.w * p.w;
        }
    }
    #pragma unroll
    for (int t = 0; t < 9; t++) {
        float a = acc[t];
        #pragma unroll
        for (int off = 16; off; off >>= 1) a += __shfl_xor_sync(0xffffffffu, a, off);
        if (l == 0) {
            if (d < DIM) g_P1T[t * DIM + d] = a;
            else         g_C3[t] = a;
        }
    }
}

// ---------------------------------------------------------------------------
// prep_c: fused silu(c) -> bf16 hi/lo packed A' write  +  t3 dot products
// ---------------------------------------------------------------------------
__global__ __launch_bounds__(256) void prep_c(const float* __restrict__ cin) {
    __shared__ float sP[9][DIM];
    __shared__ float sC[9];
    const int tid = threadIdx.x, w = tid >> 5, l = tid & 31;
    for (int i = tid; i < 9 * DIM; i += 256) (&sP[0][0])[i] = g_P1T[i];
    if (tid < 9) sC[tid] = g_C3[tid];
    __syncthreads();
    const int b = blockIdx.x * 8 + w;
    float acc[9];
    #pragma unroll
    for (int t = 0; t < 9; t++) acc[t] = 0.f;
    const float4* cv = reinterpret_cast<const float4*>(cin + (size_t)b * DIM);
    __nv_bfloat16* ap = g_Ap + (size_t)b * KP;
    #pragma unroll
    for (int j = 0; j < 4; j++) {
        int idx = j * 32 + l;
        float4 v = cv[idx];
        float s[4] = { silu_f(v.x), silu_f(v.y), silu_f(v.z), silu_f(v.w) };
        union U { __nv_bfloat16 b[4]; uint2 u; } hi, lo;
        #pragma unroll
        for (int e = 0; e < 4; e++) {
            __nv_bfloat16 h = __float2bfloat16(s[e]);
            hi.b[e] = h;
            lo.b[e] = __float2bfloat16(s[e] - __bfloat162float(h));
        }
        int kb = idx * 4;
        *reinterpret_cast<uint2*>(ap + kb)        = hi.u;
        *reinterpret_cast<uint2*>(ap + 512 + kb)  = lo.u;
        *reinterpret_cast<uint2*>(ap + 1024 + kb) = hi.u;
        #pragma unroll
        for (int t = 0; t < 9; t++) {
            float4 p = reinterpret_cast<const float4*>(sP[t])[idx];
            acc[t] += s[0] * p.x + s[1] * p.y + s[2] * p.z + s[3] * p.w;
        }
    }
    #pragma unroll
    for (int t = 0; t < 9; t++) {
        float a = acc[t];
        #pragma unroll
        for (int off = 16; off; off >>= 1) a += __shfl_xor_sync(0xffffffffu, a, off);
        if (l == 0) g_T3[(size_t)b * 9 + t] = a + sC[t];
    }
}

// ---------------------------------------------------------------------------
// prep_w2t: B'[n][*] from W_mod[k, 512+n] (tiled transpose + hi/lo split)
// ---------------------------------------------------------------------------
__global__ void prep_w2t(const float* __restrict__ Wmod) {
    __shared__ float tile[32][33];
    int tx = threadIdx.x, ty = threadIdx.y;
    int n0 = blockIdx.x * 32, k0 = blockIdx.y * 32;
    tile[ty][tx] = Wmod[(size_t)(k0 + ty) * (2 * DIM) + DIM + n0 + tx];
    __syncthreads();
    float v = tile[tx][ty];
    __nv_bfloat16 h = __float2bfloat16(v);
    __nv_bfloat16 lo = __float2bfloat16(v - __bfloat162float(h));
    size_t base = (size_t)(n0 + ty) * KP + (k0 + tx);
    g_Bp[base]        = h;
    g_Bp[base + 512]  = h;
    g_Bp[base + 1024] = lo;
}

// ---------------------------------------------------------------------------
// scale GEMM (R7 measured-best config, 26.5us): [4096,512] = A'[4096,1536]@B'^T
// CTA 128x128, 256 threads (8 warps, warp 32x64), 4-stage cp.async + ldmatrix
// ---------------------------------------------------------------------------
#define TM 128
#define TN 128
#define TK 64
#define NSTAGE 4
#define A_ST_B (TM * TK * 2)              // 16384 bytes
#define B_ST_B (TN * TK * 2)              // 16384 bytes
#define STAGE_B (A_ST_B + B_ST_B)         // 32768
#define GSMEM (STAGE_B * NSTAGE)          // 131072

__global__ __launch_bounds__(256, 1) void scale_gemm(const float* __restrict__ bmod) {
    extern __shared__ __align__(128) char sm[];
    const uint32_t sbase = smem_u32(sm);
    const int tid = threadIdx.x;
    const int wid = tid >> 5, l = tid & 31;
    const int wm = wid >> 1, wn = wid & 1;
    const int m0 = blockIdx.x * TM, n0 = blockIdx.y * TN;

    auto load_stage = [&](int st, int chunk) {
        uint32_t abase = sbase + st * STAGE_B;
        uint32_t bbase = abase + A_ST_B;
        int k0 = chunk * TK;
        #pragma unroll
        for (int i = 0; i < 4; i++) {
            int id = tid + i * 256;
            int row = id >> 3, kc = id & 7;
            uint32_t dst = abase + row * 128 + ((kc ^ (row & 7)) << 4);
            cp16(dst, g_Ap + (size_t)(m0 + row) * KP + k0 + kc * 8);
        }
        #pragma unroll
        for (int i = 0; i < 4; i++) {
            int id = tid + i * 256;
            int row = id >> 3, kc = id & 7;
            uint32_t dst = bbase + row * 128 + ((kc ^ (row & 7)) << 4);
            cp16(dst, g_Bp + (size_t)(n0 + row) * KP + k0 + kc * 8);
        }
    };

    float acc[2][8][4];
    #pragma unroll
    for (int mt = 0; mt < 2; mt++)
        #pragma unroll
        for (int nt = 0; nt < 8; nt++)
            #pragma unroll
            for (int e = 0; e < 4; e++) acc[mt][nt][e] = 0.f;

    #pragma unroll
    for (int s = 0; s < 3; s++) { load_stage(s, s); CP_COMMIT(); }

    const int NCHUNK = KP / TK;            // 24
    for (int it = 0; it < NCHUNK; ++it) {
        CP_WAIT(2);
        __syncthreads();
        if (it + 3 < NCHUNK) load_stage((it + 3) & 3, it + 3);
        CP_COMMIT();
        uint32_t abase = sbase + (it & 3) * STAGE_B;
        uint32_t bbase = abase + A_ST_B;
        #pragma unroll
        for (int kk = 0; kk < 4; kk++) {
            int kc0 = kk * 2 + (l >> 4);
            uint32_t a[2][4], b[4][4];
            #pragma unroll
            for (int mt = 0; mt < 2; mt++) {
                int row = wm * 32 + mt * 16 + (l & 15);
                ldmx4(a[mt], abase + row * 128 + ((kc0 ^ (row & 7)) << 4));
            }
            #pragma unroll
            for (int g = 0; g < 4; g++) {
                int row = wn * 64 + g * 16 + (l & 15);
                ldmx4(b[g], bbase + row * 128 + ((kc0 ^ (row & 7)) << 4));
            }
            #pragma unroll
            for (int mt = 0; mt < 2; mt++)
                #pragma unroll
                for (int g = 0; g < 4; g++) {
                    uint32_t b0[2] = { b[g][0], b[g][2] };
                    uint32_t b1[2] = { b[g][1], b[g][3] };
                    mma_bf16(acc[mt][2 * g],     a[mt], b0);
                    mma_bf16(acc[mt][2 * g + 1], a[mt], b1);
                }
        }
    }
    CP_WAIT(0);

    const int fr = l >> 2, fc = (l & 3) * 2;
    #pragma unroll
    for (int mt = 0; mt < 2; mt++) {
        int m = m0 + wm * 32 + mt * 16 + fr;
        #pragma unroll
        for (int nt = 0; nt < 8; nt++) {
            int n = n0 + wn * 64 + nt * 8 + fc;
            float2 bv = *reinterpret_cast<const float2*>(bmod + DIM + n);
            float2 v0 = make_float2(acc[mt][nt][0] + bv.x, acc[mt][nt][1] + bv.y);
            float2 v1 = make_float2(acc[mt][nt][2] + bv.x, acc[mt][nt][3] + bv.y);
            *reinterpret_cast<float2*>(g_scale + (size_t)m * DIM + n) = v0;
            *reinterpret_cast<float2*>(g_scale + (size_t)(m + 8) * DIM + n) = v1;
        }
    }
}

// ---------------------------------------------------------------------------
// final: cp.async double-buffered x pipeline. Per block: BPB batches.
// 6 warps x 3 rows; x and scale staged via cp.async (deep DMA queue -> DRAM
// latency hidden); x re-read from smem (no register x cache).
// xm = (v - mu) * (rstd*(1+s)),  g = fma(s, rst, rst).
// ---------------------------------------------------------------------------
#define BPB 4
#define XF (NN * DIM)                 // 8704 floats per batch
// dynamic smem layout (float offsets)
#define SM_WG 0                       // [9][512]
#define SM_L  (SM_WG + 9 * DIM)       // 4608
#define SM_Q  (SM_L + NN * NN)        // 4897
#define SM_T3 (SM_Q + NN * NN)        // 5186
#define SM_Y4 (SM_T3 + 9)             // 5195  [3][17][3][4]
#define SM_YS (SM_Y4 + 612)           // 5807  [3][17][3]
#define SM_X  5960                    // [2][8704]  (16B aligned: 5960*4=23840)
#define SM_SC (SM_X + 2 * XF)         // 23368 [2][512]
#define SM_F_TOT (SM_SC + 2 * DIM)    // 24392 floats
#define GSMEM_F (SM_F_TOT * 4)        // 97568 bytes

__global__ __launch_bounds__(192) void final_kernel(const float* __restrict__ x,
                                                    const float* __restrict__ Wg,
                                                    const float* __restrict__ bg,
                                                    float* __restrict__ out) {
    extern __shared__ __align__(16) float sf[];
    const uint32_t sbase = smem_u32(sf);
    const int tid = threadIdx.x;
    const int w = tid >> 5;
    const int l = tid & 31;

    auto stage = [&](int bb, int buf) {
        const int b = blockIdx.x * BPB + bb;
        const float* xp = x + (size_t)b * XF;
        uint32_t dstx = sbase + (SM_X + buf * XF) * 4;
        #pragma unroll
        for (int i = 0; i < 12; i++) {
            int id = tid + i * 192;
            if (id < XF / 4) cp16(dstx + id * 16, xp + id * 4);
        }
        if (tid < DIM / 4)
            cp16(sbase + (SM_SC + buf * DIM) * 4 + tid * 16,
                 g_scale + (size_t)b * DIM + tid * 4);
    };

    // kick off batch 0 prefetch, then do static staging under it
    stage(0, 0); CP_COMMIT();

    for (int i = tid; i < 9 * DIM; i += 192) {
        int k = i / (DIM * 3), r = i % (DIM * 3), c = r / 3, o = r % 3;
        sf[SM_WG + (k * 3 + o) * DIM + c] = Wg[i];
    }
    for (int i = tid; i < NN * NN; i += 192) {
        sf[SM_L + i] = g_L[i];
        sf[SM_Q + i] = g_Q[i];
    }

    for (int bb = 0; bb < BPB; ++bb) {
        const int b = blockIdx.x * BPB + bb;
        const int buf = bb & 1;
        CP_WAIT(0);
        __syncthreads();                      // buffer ready + prior compute done
        if (bb + 1 < BPB) { stage(bb + 1, buf ^ 1); CP_COMMIT(); }
        if (tid < 9) sf[SM_T3 + tid] = g_T3[(size_t)b * 9 + tid];

        const float* sx  = sf + SM_X + buf * XF;
        const float* ssc = sf + SM_SC + buf * DIM;

        // --- stats (from smem) ---
        float nmu[3], rstd[3];
        #pragma unroll
        for (int r = 0; r < 3; r++) {
            int n = w * 3 + r; if (n > NN - 1) n = NN - 1;
            const float4* xp = reinterpret_cast<const float4*>(sx + n * DIM);
            float s = 0.f, s2 = 0.f;
            #pragma unroll
            for (int j = 0; j < 4; j++) {
                float4 v = xp[j * 32 + l];
                s  += (v.x + v.y) + (v.z + v.w);
                s2 += (v.x * v.x + v.y * v.y) + (v.z * v.z + v.w * v.w);
            }
            #pragma unroll
            for (int off = 16; off; off >>= 1) {
                s  += __shfl_xor_sync(0xffffffffu, s,  off);
                s2 += __shfl_xor_sync(0xffffffffu, s2, off);
            }
            float mu  = s * (1.f / DIM);
            float var = s2 * (1.f / DIM) - mu * mu;
            nmu[r]  = -mu;
            rstd[r] = rsqrtf(var + 1e-6f);
        }

        // --- dot loop (x re-read from smem) ---
        u64 acc2[3][9];
        #pragma unroll
        for (int r = 0; r < 3; r++)
            #pragma unroll
            for (int t = 0; t < 9; t++) acc2[r][t] = 0ull;

        #pragma unroll
        for (int j = 0; j < 4; j++) {
            const int idx = j * 32 + l;
            float4 sc = reinterpret_cast<const float4*>(ssc)[idx];
            u64 sc01 = pack2(sc.x, sc.y), sc23 = pack2(sc.z, sc.w);
            u64 wv01[9], wv23[9];
            #pragma unroll
            for (int t = 0; t < 9; t++) {
                float4 wv = reinterpret_cast<const float4*>(sf + SM_WG + t * DIM)[idx];
                wv01[t] = pack2(wv.x, wv.y);
                wv23[t] = pack2(wv.z, wv.w);
            }
            #pragma unroll
            for (int r = 0; r < 3; r++) {
                int n = w * 3 + r; if (n > NN - 1) n = NN - 1;
                u64 rst2 = pack2(rstd[r], rstd[r]);
                u64 nmu2 = pack2(nmu[r], nmu[r]);
                float4 v = reinterpret_cast<const float4*>(sx + n * DIM)[idx];
                u64 v01 = pack2(v.x, v.y), v23 = pack2(v.z, v.w);
                u64 g01, g23, t01, t23, xm01, xm23;
                FMA23(g01, sc01, rst2, rst2);      // (1+s)*rstd
                FMA23(g23, sc23, rst2, rst2);
                ADD2(t01, v01, nmu2);
                ADD2(t23, v23, nmu2);
                MUL2(xm01, t01, g01);
                MUL2(xm23, t23, g23);
                #pragma unroll
                for (int t = 0; t < 9; t++) {
                    FMA2(acc2[r][t], xm01, wv01[t]);
                    FMA2(acc2[r][t], xm23, wv23[t]);
                }
            }
        }

        // --- 3-step butterfly -> 4 partials, lanes 0-3 write ---
        #pragma unroll
        for (int r = 0; r < 3; r++) {
            int n = w * 3 + r;
            #pragma unroll
            for (int t = 0; t < 9; t++) {
                F2 u; u.u = acc2[r][t];
                float a = u.f.x + u.f.y;
                a += __shfl_xor_sync(0xffffffffu, a, 16);
                a += __shfl_xor_sync(0xffffffffu, a, 8);
                a += __shfl_xor_sync(0xffffffffu, a, 4);
                if (l < 4 && n < NN)
                    sf[SM_Y4 + (((t / 3) * NN + n) * OUTC + (t % 3)) * 4 + l] = a;
            }
        }
        __syncthreads();
        if (tid < 3 * NN * OUTC) {               // 153
            const float* p = sf + SM_Y4 + tid * 4;
            sf[SM_YS + tid] = (p[0] + p[1]) + (p[2] + p[3]);
        }
        __syncthreads();

        if (tid < NN * OUTC) {
            int n = tid / OUTC, o = tid - n * OUTC;
            float t31 = sf[SM_T3 + 3 + o], t32 = sf[SM_T3 + 6 + o];
            float res = sf[SM_YS + n * OUTC + o] + sf[SM_T3 + o] + bg[o];
            #pragma unroll
            for (int m = 0; m < NN; m++)
                res += sf[SM_L + n * NN + m] * (sf[SM_YS + NN * OUTC + m * OUTC + o] + t31)
                     + sf[SM_Q + n * NN + m] * (sf[SM_YS + 2 * NN * OUTC + m * OUTC + o] + t32);
            out[((size_t)b * NN + n) * OUTC + o] = res;
        }
    }
}

// ---------------------------------------------------------------------------
extern "C" void kernel_launch(void* const* d_in, const int* in_sizes, int n_in,
                              void* d_out, int out_size) {
    const float* x     = (const float*)d_in[0];  // [4096,17,512]
    const float* adj   = (const float*)d_in[1];  // [17,17]
    const float* c     = (const float*)d_in[2];  // [4096,1,512]
    const float* W_mod = (const float*)d_in[3];  // [512,1024]
    const float* b_mod = (const float*)d_in[4];  // [1024]
    const float* Wg    = (const float*)d_in[5];  // [3,512,3]
    const float* bg    = (const float*)d_in[6];  // [3]
    float* out = (float*)d_out;                  // [4096,17,3] f32

    cudaFuncSetAttribute(scale_gemm, cudaFuncAttributeMaxDynamicSharedMemorySize, GSMEM);
    cudaFuncSetAttribute(final_kernel, cudaFuncAttributeMaxDynamicSharedMemorySize, GSMEM_F);

    setup_kernel<<<66, 256>>>(W_mod, b_mod, Wg, adj);
    prep_w2t<<<dim3(16, 16), dim3(32, 32)>>>(W_mod);
    prep_c<<<BATCH / 8, 256>>>(c);
    scale_gemm<<<dim3(BATCH / TM, DIM / TN), 256, GSMEM>>>(b_mod);
    final_kernel<<<BATCH / BPB, 192, GSMEM_F>>>(x, Wg, bg, out);
}

// round 11
// speedup vs baseline: 1.3991x; 1.0339x over previous
#include <cuda_runtime.h>
#include <cuda_bf16.h>
#include <cstdint>

#define BATCH 4096
#define NN 17
#define DIM 512
#define OUTC 3
#define KP 1536   // packed K = [hi|lo|hi] x 512

// ----------------------------- device scratch ------------------------------
__device__ __align__(16) __nv_bfloat16 g_Ap[(size_t)BATCH * KP];  // [Ahi|Alo|Ahi]
__device__ __align__(16) __nv_bfloat16 g_Bp[(size_t)DIM * KP];    // [Bhi|Bhi|Blo] (B^T rows)
__device__ __align__(16) float g_scale[(size_t)BATCH * DIM];
__device__ float g_P1T[9 * DIM];
__device__ float g_C3[9];
__device__ float g_T3[(size_t)BATCH * 9];
__device__ float g_L[NN * NN];
__device__ float g_Q[NN * NN];

__device__ __forceinline__ float silu_f(float v) { return v / (1.f + __expf(-v)); }

__device__ __forceinline__ uint32_t smem_u32(const void* p) {
    uint32_t a;
    asm("{ .reg .u64 t; cvta.to.shared.u64 t, %1; cvt.u32.u64 %0, t; }" : "=r"(a) : "l"(p));
    return a;
}
__device__ __forceinline__ void cp16(uint32_t dst, const void* src) {
    asm volatile("cp.async.cg.shared.global [%0], [%1], 16;" :: "r"(dst), "l"(src));
}
#define CP_COMMIT() asm volatile("cp.async.commit_group;" ::: "memory")
#define CP_WAIT(n)  asm volatile("cp.async.wait_group %0;" :: "n"(n) : "memory")

__device__ __forceinline__ void ldmx4(uint32_t* r, uint32_t addr) {
    asm volatile("ldmatrix.sync.aligned.m8n8.x4.shared.b16 {%0,%1,%2,%3}, [%4];"
                 : "=r"(r[0]), "=r"(r[1]), "=r"(r[2]), "=r"(r[3]) : "r"(addr));
}
__device__ __forceinline__ void mma_bf16(float* c, const uint32_t* a, const uint32_t* b) {
    asm volatile(
        "mma.sync.aligned.m16n8k16.row.col.f32.bf16.bf16.f32 "
        "{%0,%1,%2,%3}, {%4,%5,%6,%7}, {%8,%9}, {%0,%1,%2,%3};"
        : "+f"(c[0]), "+f"(c[1]), "+f"(c[2]), "+f"(c[3])
        : "r"(a[0]), "r"(a[1]), "r"(a[2]), "r"(a[3]), "r"(b[0]), "r"(b[1]));
}

// -------- packed f32x2 (PTX ISA 8.6, sm_100+ baseline; NOT arch-'a' gated) --
typedef unsigned long long u64;
union F2 { float2 f; u64 u; };
__device__ __forceinline__ u64 pack2(float a, float b) {
    F2 t; t.f = make_float2(a, b); return t.u;
}
#define FMA2(acc, a, b)   asm("fma.rn.f32x2 %0, %1, %2, %0;" : "+l"(acc) : "l"(a), "l"(b))
#define MUL2(d, a, b)     asm("mul.rn.f32x2 %0, %1, %2;"     : "=l"(d)  : "l"(a), "l"(b))
#define ADD2(acc, a)      asm("add.rn.f32x2 %0, %0, %1;"     : "+l"(acc) : "l"(a))

// ---------------------------------------------------------------------------
// setup: blocks 0..64 compute P1^T (+C3); block 65 computes L and Q
// ---------------------------------------------------------------------------
__global__ __launch_bounds__(256) void setup_kernel(const float* __restrict__ Wmod,
                                                    const float* __restrict__ bmod,
                                                    const float* __restrict__ Wg,
                                                    const float* __restrict__ adj) {
    const int tid = threadIdx.x;
    if (blockIdx.x == 65) {
        __shared__ float sD[NN];
        __shared__ float sL[NN * NN];
        if (tid < NN) {
            float s = 0.f;
            #pragma unroll
            for (int m = 0; m < NN; m++) s += adj[tid * NN + m];
            sD[tid] = rsqrtf(s);
        }
        __syncthreads();
        for (int i = tid; i < NN * NN; i += 256) {
            int n = i / NN, m = i % NN;
            float v = ((n == m) ? 1.f : 0.f) - sD[n] * adj[i] * sD[m];
            sL[i] = v; g_L[i] = v;
        }
        __syncthreads();
        for (int i = tid; i < NN * NN; i += 256) {
            int n = i / NN, m = i % NN;
            float s = 0.f;
            #pragma unroll
            for (int j = 0; j < NN; j++) s += sL[n * NN + j] * sL[j * NN + m];
            g_Q[i] = 2.f * s - ((n == m) ? 1.f : 0.f);
        }
        return;
    }
    __shared__ float sWgT[9][DIM];
    const int w = tid >> 5, l = tid & 31;
    for (int i = tid; i < 9 * DIM; i += 256) {
        int k = i / (DIM * 3), r = i % (DIM * 3), c = r / 3, o = r % 3;
        sWgT[k * 3 + o][c] = Wg[i];
    }
    __syncthreads();
    int d = blockIdx.x * 8 + w;
    if (d > DIM) return;
    float acc[9];
    #pragma unroll
    for (int t = 0; t < 9; t++) acc[t] = 0.f;
    #pragma unroll
    for (int j = 0; j < 4; j++) {
        int idx = j * 32 + l;
        float4 wv = (d < DIM)
            ? reinterpret_cast<const float4*>(Wmod + (size_t)d * 2 * DIM)[idx]
            : reinterpret_cast<const float4*>(bmod)[idx];
        #pragma unroll
        for (int t = 0; t < 9; t++) {
            float4 p = reinterpret_cast<const float4*>(sWgT[t])[idx];
            acc[t] += wv.x * p.x + wv.y * p.y + wv.z * p.z + wv.w * p.w;
        }
    }
    #pragma unroll
    for (int t = 0; t < 9; t++) {
        float a = acc[t];
        #pragma unroll
        for (int off = 16; off; off >>= 1) a += __shfl_xor_sync(0xffffffffu, a, off);
        if (l == 0) {
            if (d < DIM) g_P1T[t * DIM + d] = a;
            else         g_C3[t] = a;
        }
    }
}

// ---------------------------------------------------------------------------
// prep_c: fused silu(c) -> bf16 hi/lo packed A' write  +  t3 dot products
// ---------------------------------------------------------------------------
__global__ __launch_bounds__(256) void prep_c(const float* __restrict__ cin) {
    __shared__ float sP[9][DIM];
    __shared__ float sC[9];
    const int tid = threadIdx.x, w = tid >> 5, l = tid & 31;
    for (int i = tid; i < 9 * DIM; i += 256) (&sP[0][0])[i] = g_P1T[i];
    if (tid < 9) sC[tid] = g_C3[tid];
    __syncthreads();
    const int b = blockIdx.x * 8 + w;
    float acc[9];
    #pragma unroll
    for (int t = 0; t < 9; t++) acc[t] = 0.f;
    const float4* cv = reinterpret_cast<const float4*>(cin + (size_t)b * DIM);
    __nv_bfloat16* ap = g_Ap + (size_t)b * KP;
    #pragma unroll
    for (int j = 0; j < 4; j++) {
        int idx = j * 32 + l;
        float4 v = cv[idx];
        float s[4] = { silu_f(v.x), silu_f(v.y), silu_f(v.z), silu_f(v.w) };
        union U { __nv_bfloat16 b[4]; uint2 u; } hi, lo;
        #pragma unroll
        for (int e = 0; e < 4; e++) {
            __nv_bfloat16 h = __float2bfloat16(s[e]);
            hi.b[e] = h;
            lo.b[e] = __float2bfloat16(s[e] - __bfloat162float(h));
        }
        int kb = idx * 4;
        *reinterpret_cast<uint2*>(ap + kb)        = hi.u;
        *reinterpret_cast<uint2*>(ap + 512 + kb)  = lo.u;
        *reinterpret_cast<uint2*>(ap + 1024 + kb) = hi.u;
        #pragma unroll
        for (int t = 0; t < 9; t++) {
            float4 p = reinterpret_cast<const float4*>(sP[t])[idx];
            acc[t] += s[0] * p.x + s[1] * p.y + s[2] * p.z + s[3] * p.w;
        }
    }
    #pragma unroll
    for (int t = 0; t < 9; t++) {
        float a = acc[t];
        #pragma unroll
        for (int off = 16; off; off >>= 1) a += __shfl_xor_sync(0xffffffffu, a, off);
        if (l == 0) g_T3[(size_t)b * 9 + t] = a + sC[t];
    }
}

// ---------------------------------------------------------------------------
// prep_w2t: B'[n][*] from W_mod[k, 512+n] (tiled transpose + hi/lo split)
// ---------------------------------------------------------------------------
__global__ void prep_w2t(const float* __restrict__ Wmod) {
    __shared__ float tile[32][33];
    int tx = threadIdx.x, ty = threadIdx.y;
    int n0 = blockIdx.x * 32, k0 = blockIdx.y * 32;
    tile[ty][tx] = Wmod[(size_t)(k0 + ty) * (2 * DIM) + DIM + n0 + tx];
    __syncthreads();
    float v = tile[tx][ty];
    __nv_bfloat16 h = __float2bfloat16(v);
    __nv_bfloat16 lo = __float2bfloat16(v - __bfloat162float(h));
    size_t base = (size_t)(n0 + ty) * KP + (k0 + tx);
    g_Bp[base]        = h;
    g_Bp[base + 512]  = h;
    g_Bp[base + 1024] = lo;
}

// ---------------------------------------------------------------------------
// scale GEMM (measured-best config, 26.4us): [4096,512] = A'[4096,1536]@B'^T
// CTA 128x128, 256 threads (8 warps, warp 32x64), 4-stage cp.async + ldmatrix
// ---------------------------------------------------------------------------
#define TM 128
#define TN 128
#define TK 64
#define NSTAGE 4
#define A_ST_B (TM * TK * 2)
#define B_ST_B (TN * TK * 2)
#define STAGE_B (A_ST_B + B_ST_B)
#define GSMEM (STAGE_B * NSTAGE)

__global__ __launch_bounds__(256, 1) void scale_gemm(const float* __restrict__ bmod) {
    extern __shared__ __align__(128) char sm[];
    const uint32_t sbase = smem_u32(sm);
    const int tid = threadIdx.x;
    const int wid = tid >> 5, l = tid & 31;
    const int wm = wid >> 1, wn = wid & 1;
    const int m0 = blockIdx.x * TM, n0 = blockIdx.y * TN;

    auto load_stage = [&](int st, int chunk) {
        uint32_t abase = sbase + st * STAGE_B;
        uint32_t bbase = abase + A_ST_B;
        int k0 = chunk * TK;
        #pragma unroll
        for (int i = 0; i < 4; i++) {
            int id = tid + i * 256;
            int row = id >> 3, kc = id & 7;
            uint32_t dst = abase + row * 128 + ((kc ^ (row & 7)) << 4);
            cp16(dst, g_Ap + (size_t)(m0 + row) * KP + k0 + kc * 8);
        }
        #pragma unroll
        for (int i = 0; i < 4; i++) {
            int id = tid + i * 256;
            int row = id >> 3, kc = id & 7;
            uint32_t dst = bbase + row * 128 + ((kc ^ (row & 7)) << 4);
            cp16(dst, g_Bp + (size_t)(n0 + row) * KP + k0 + kc * 8);
        }
    };

    float acc[2][8][4];
    #pragma unroll
    for (int mt = 0; mt < 2; mt++)
        #pragma unroll
        for (int nt = 0; nt < 8; nt++)
            #pragma unroll
            for (int e = 0; e < 4; e++) acc[mt][nt][e] = 0.f;

    #pragma unroll
    for (int s = 0; s < 3; s++) { load_stage(s, s); CP_COMMIT(); }

    const int NCHUNK = KP / TK;            // 24
    for (int it = 0; it < NCHUNK; ++it) {
        CP_WAIT(2);
        __syncthreads();
        if (it + 3 < NCHUNK) load_stage((it + 3) & 3, it + 3);
        CP_COMMIT();
        uint32_t abase = sbase + (it & 3) * STAGE_B;
        uint32_t bbase = abase + A_ST_B;
        #pragma unroll
        for (int kk = 0; kk < 4; kk++) {
            int kc0 = kk * 2 + (l >> 4);
            uint32_t a[2][4], b[4][4];
            #pragma unroll
            for (int mt = 0; mt < 2; mt++) {
                int row = wm * 32 + mt * 16 + (l & 15);
                ldmx4(a[mt], abase + row * 128 + ((kc0 ^ (row & 7)) << 4));
            }
            #pragma unroll
            for (int g = 0; g < 4; g++) {
                int row = wn * 64 + g * 16 + (l & 15);
                ldmx4(b[g], bbase + row * 128 + ((kc0 ^ (row & 7)) << 4));
            }
            #pragma unroll
            for (int mt = 0; mt < 2; mt++)
                #pragma unroll
                for (int g = 0; g < 4; g++) {
                    uint32_t b0[2] = { b[g][0], b[g][2] };
                    uint32_t b1[2] = { b[g][1], b[g][3] };
                    mma_bf16(acc[mt][2 * g],     a[mt], b0);
                    mma_bf16(acc[mt][2 * g + 1], a[mt], b1);
                }
        }
    }
    CP_WAIT(0);

    const int fr = l >> 2, fc = (l & 3) * 2;
    #pragma unroll
    for (int mt = 0; mt < 2; mt++) {
        int m = m0 + wm * 32 + mt * 16 + fr;
        #pragma unroll
        for (int nt = 0; nt < 8; nt++) {
            int n = n0 + wn * 64 + nt * 8 + fc;
            float2 bv = *reinterpret_cast<const float2*>(bmod + DIM + n);
            float2 v0 = make_float2(acc[mt][nt][0] + bv.x, acc[mt][nt][1] + bv.y);
            float2 v1 = make_float2(acc[mt][nt][2] + bv.x, acc[mt][nt][3] + bv.y);
            *reinterpret_cast<float2*>(g_scale + (size_t)m * DIM + n) = v0;
            *reinterpret_cast<float2*>(g_scale + (size_t)(m + 8) * DIM + n) = v1;
        }
    }
}

// ---------------------------------------------------------------------------
// final: single-pass u-trick + deferred combine.
//   d_t[n] = sum_c x[n,c]*(1+s_c)*Wg[t,c]   (raw x; mu,var in same pass)
//   slot 17 = ones-row -> u_t = sum_c (1+s_c)Wg[t,c]
//   y_t[n] = rstd_n*(d_t[n] - mu_n*u_t)
//   out = y0 + t3_0 + bg + L(y1+t3_1) + Q(y2+t3_2)
// 6 warps x 3 slots (18 slots = 17 rows + u). 1 sync/batch + 2 at end.
// ---------------------------------------------------------------------------
#define BPB 4
#define XROWS 18
#define XF (XROWS * DIM)              // 9216 floats per buffer
// dynamic smem layout (float offsets)
#define SM_WG 0                       // [9][512] = 4608
#define SM_L  (SM_WG + 9 * DIM)       // 4608
#define SM_Q  (SM_L + NN * NN)        // 4897
#define SM_T3 (SM_Q + NN * NN)        // 5186  [4][9]
#define SM_D  (SM_T3 + 4 * 9)         // 5222  [4][18][11][2] = 1584
#define SM_Y  (SM_D + 4 * 18 * 11 * 2)// 6806  [4][3][17][3] = 612
#define SM_X  7424                    // [2][9216] (7424*4 % 16 == 0)
#define SM_SC (SM_X + 2 * XF)         // 25856 [2][512]
#define SM_F_TOT (SM_SC + 2 * DIM)    // 26880 floats
#define GSMEM_F (SM_F_TOT * 4)        // 107520 bytes

__global__ __launch_bounds__(192, 2) void final_kernel(const float* __restrict__ x,
                                                       const float* __restrict__ Wg,
                                                       const float* __restrict__ bg,
                                                       float* __restrict__ out) {
    extern __shared__ __align__(16) float sf[];
    const uint32_t sbase = smem_u32(sf);
    const int tid = threadIdx.x;
    const int w = tid >> 5;
    const int l = tid & 31;

    auto stage = [&](int bb, int buf) {
        const int b = blockIdx.x * BPB + bb;
        const float* xp = x + (size_t)b * (NN * DIM);
        uint32_t dstx = sbase + (SM_X + buf * XF) * 4;
        #pragma unroll
        for (int i = 0; i < 12; i++) {
            int id = tid + i * 192;
            if (id < (NN * DIM) / 4) cp16(dstx + id * 16, xp + id * 4);
        }
        if (tid < DIM / 4)
            cp16(sbase + (SM_SC + buf * DIM) * 4 + tid * 16,
                 g_scale + (size_t)b * DIM + tid * 4);
    };

    stage(0, 0); CP_COMMIT();

    // static staging + ones-rows (slot 17 of both x buffers)
    for (int i = tid; i < 9 * DIM; i += 192) {
        int k = i / (DIM * 3), r = i % (DIM * 3), c = r / 3, o = r % 3;
        sf[SM_WG + (k * 3 + o) * DIM + c] = Wg[i];
    }
    for (int i = tid; i < NN * NN; i += 192) {
        sf[SM_L + i] = g_L[i];
        sf[SM_Q + i] = g_Q[i];
    }
    for (int i = tid; i < DIM; i += 192) {
        sf[SM_X + NN * DIM + i]      = 1.f;
        sf[SM_X + XF + NN * DIM + i] = 1.f;
    }

    for (int bb = 0; bb < BPB; ++bb) {
        const int b = blockIdx.x * BPB + bb;
        const int buf = bb & 1;
        CP_WAIT(0);
        __syncthreads();                      // buffer ready + prior compute done
        if (bb + 1 < BPB) { stage(bb + 1, buf ^ 1); CP_COMMIT(); }
        if (tid < 9) sf[SM_T3 + bb * 9 + tid] = g_T3[(size_t)b * 9 + tid];

        const float* sx  = sf + SM_X + buf * XF;
        const float* ssc = sf + SM_SC + buf * DIM;

        // single pass: 9 dots + s + s2 per slot (slots = 3w+r, 0..17)
        u64 acc2[3][11];
        #pragma unroll
        for (int r = 0; r < 3; r++)
            #pragma unroll
            for (int t = 0; t < 11; t++) acc2[r][t] = 0ull;

        #pragma unroll
        for (int j = 0; j < 4; j++) {
            const int idx = j * 32 + l;
            float4 sc = reinterpret_cast<const float4*>(ssc)[idx];
            u64 g01 = pack2(sc.x + 1.f, sc.y + 1.f);
            u64 g23 = pack2(sc.z + 1.f, sc.w + 1.f);
            u64 wv01[9], wv23[9];
            #pragma unroll
            for (int t = 0; t < 9; t++) {
                float4 wv = reinterpret_cast<const float4*>(sf + SM_WG + t * DIM)[idx];
                wv01[t] = pack2(wv.x, wv.y);
                wv23[t] = pack2(wv.z, wv.w);
            }
            #pragma unroll
            for (int r = 0; r < 3; r++) {
                const int n = w * 3 + r;      // 0..17
                float4 v = reinterpret_cast<const float4*>(sx + n * DIM)[idx];
                u64 v01 = pack2(v.x, v.y), v23 = pack2(v.z, v.w);
                u64 xm01, xm23;
                MUL2(xm01, v01, g01);
                MUL2(xm23, v23, g23);
                ADD2(acc2[r][9], v01); ADD2(acc2[r][9], v23);     // s
                FMA2(acc2[r][10], v01, v01); FMA2(acc2[r][10], v23, v23);  // s2
                #pragma unroll
                for (int t = 0; t < 9; t++) {
                    FMA2(acc2[r][t], xm01, wv01[t]);
                    FMA2(acc2[r][t], xm23, wv23[t]);
                }
            }
        }

        // 4-step butterfly -> 2 partials, lanes 0-1 write
        #pragma unroll
        for (int r = 0; r < 3; r++) {
            const int n = w * 3 + r;
            #pragma unroll
            for (int t = 0; t < 11; t++) {
                F2 u; u.u = acc2[r][t];
                float a = u.f.x + u.f.y;
                a += __shfl_xor_sync(0xffffffffu, a, 16);
                a += __shfl_xor_sync(0xffffffffu, a, 8);
                a += __shfl_xor_sync(0xffffffffu, a, 4);
                a += __shfl_xor_sync(0xffffffffu, a, 2);
                if (l < 2)
                    sf[SM_D + (((bb * 18 + n) * 11) + t) * 2 + l] = a;
            }
        }
        // no sync here: next iteration's top sync covers it
    }
    __syncthreads();

    // phase A: y[b][k][n][o] = rstd*(d - mu*u)
    for (int i = tid; i < 4 * 153; i += 192) {
        int b4 = i / 153, r = i % 153;
        int k = r / 51, rr = r % 51, n = rr / 3, o = rr % 3;
        int t = k * 3 + o;
        const float* dbase = sf + SM_D + ((b4 * 18 + n) * 11) * 2;
        const float* ubase = sf + SM_D + ((b4 * 18 + 17) * 11) * 2;
        float d = dbase[t * 2] + dbase[t * 2 + 1];
        float u = ubase[t * 2] + ubase[t * 2 + 1];
        float s  = dbase[9 * 2]  + dbase[9 * 2 + 1];
        float s2 = dbase[10 * 2] + dbase[10 * 2 + 1];
        float mu = s * (1.f / DIM);
        float var = s2 * (1.f / DIM) - mu * mu;
        float rstd = rsqrtf(var + 1e-6f);
        sf[SM_Y + ((b4 * 3 + k) * NN + n) * OUTC + o] = rstd * (d - mu * u);
    }
    __syncthreads();

    // phase B: graph combine + t3 + bias
    for (int i = tid; i < 4 * NN * OUTC; i += 192) {
        int b4 = i / (NN * OUTC), r = i % (NN * OUTC);
        int n = r / OUTC, o = r % OUTC;
        const int b = blockIdx.x * BPB + b4;
        const float* t3 = sf + SM_T3 + b4 * 9;
        const float* y0 = sf + SM_Y + (b4 * 3 + 0) * NN * OUTC;
        const float* y1 = sf + SM_Y + (b4 * 3 + 1) * NN * OUTC;
        const float* y2 = sf + SM_Y + (b4 * 3 + 2) * NN * OUTC;
        float t31 = t3[3 + o], t32 = t3[6 + o];
        float res = y0[n * OUTC + o] + t3[o] + bg[o];
        #pragma unroll
        for (int m = 0; m < NN; m++)
            res += sf[SM_L + n * NN + m] * (y1[m * OUTC + o] + t31)
                 + sf[SM_Q + n * NN + m] * (y2[m * OUTC + o] + t32);
        out[((size_t)b * NN + n) * OUTC + o] = res;
    }
}

// ---------------------------------------------------------------------------
extern "C" void kernel_launch(void* const* d_in, const int* in_sizes, int n_in,
                              void* d_out, int out_size) {
    const float* x     = (const float*)d_in[0];  // [4096,17,512]
    const float* adj   = (const float*)d_in[1];  // [17,17]
    const float* c     = (const float*)d_in[2];  // [4096,1,512]
    const float* W_mod = (const float*)d_in[3];  // [512,1024]
    const float* b_mod = (const float*)d_in[4];  // [1024]
    const float* Wg    = (const float*)d_in[5];  // [3,512,3]
    const float* bg    = (const float*)d_in[6];  // [3]
    float* out = (float*)d_out;                  // [4096,17,3] f32

    cudaFuncSetAttribute(scale_gemm, cudaFuncAttributeMaxDynamicSharedMemorySize, GSMEM);
    cudaFuncSetAttribute(final_kernel, cudaFuncAttributeMaxDynamicSharedMemorySize, GSMEM_F);

    setup_kernel<<<66, 256>>>(W_mod, b_mod, Wg, adj);
    prep_w2t<<<dim3(16, 16), dim3(32, 32)>>>(W_mod);
    prep_c<<<BATCH / 8, 256>>>(c);
    scale_gemm<<<dim3(BATCH / TM, DIM / TN), 256, GSMEM>>>(b_mod);
    final_kernel<<<BATCH / BPB, 192, GSMEM_F>>>(x, Wg, bg, out);
}

// round 12
// speedup vs baseline: 1.4495x; 1.0361x over previous
#include <cuda_runtime.h>
#include <cuda_bf16.h>
#include <cstdint>

#define BATCH 4096
#define NN 17
#define DIM 512
#define OUTC 3
#define KP 1536   // logical packed K = [hi|lo|hi] x 512
#define KPS 1024  // stored K = [hi|lo]

// ----------------------------- device scratch ------------------------------
__device__ __align__(16) __nv_bfloat16 g_Ap[(size_t)BATCH * KPS];  // [Ahi|Alo]
__device__ __align__(16) __nv_bfloat16 g_Bp[(size_t)DIM * KPS];    // [Bhi|Blo] (B^T rows)
__device__ __align__(16) float g_scale[(size_t)BATCH * DIM];
__device__ float g_P1T[9 * DIM];
__device__ float g_C3[9];
__device__ float g_T3[(size_t)BATCH * 9];
__device__ float g_L[NN * NN];
__device__ float g_Q[NN * NN];

__device__ __forceinline__ float silu_f(float v) { return v / (1.f + __expf(-v)); }

__device__ __forceinline__ uint32_t smem_u32(const void* p) {
    uint32_t a;
    asm("{ .reg .u64 t; cvta.to.shared.u64 t, %1; cvt.u32.u64 %0, t; }" : "=r"(a) : "l"(p));
    return a;
}
__device__ __forceinline__ void cp16(uint32_t dst, const void* src) {
    asm volatile("cp.async.cg.shared.global [%0], [%1], 16;" :: "r"(dst), "l"(src));
}
#define CP_COMMIT() asm volatile("cp.async.commit_group;" ::: "memory")
#define CP_WAIT(n)  asm volatile("cp.async.wait_group %0;" :: "n"(n) : "memory")

__device__ __forceinline__ void ldmx4(uint32_t* r, uint32_t addr) {
    asm volatile("ldmatrix.sync.aligned.m8n8.x4.shared.b16 {%0,%1,%2,%3}, [%4];"
                 : "=r"(r[0]), "=r"(r[1]), "=r"(r[2]), "=r"(r[3]) : "r"(addr));
}
__device__ __forceinline__ void mma_bf16(float* c, const uint32_t* a, const uint32_t* b) {
    asm volatile(
        "mma.sync.aligned.m16n8k16.row.col.f32.bf16.bf16.f32 "
        "{%0,%1,%2,%3}, {%4,%5,%6,%7}, {%8,%9}, {%0,%1,%2,%3};"
        : "+f"(c[0]), "+f"(c[1]), "+f"(c[2]), "+f"(c[3])
        : "r"(a[0]), "r"(a[1]), "r"(a[2]), "r"(a[3]), "r"(b[0]), "r"(b[1]));
}

// -------- packed f32x2 (PTX ISA 8.6, sm_100+ baseline) ----------------------
typedef unsigned long long u64;
union F2 { float2 f; u64 u; };
__device__ __forceinline__ u64 pack2(float a, float b) {
    F2 t; t.f = make_float2(a, b); return t.u;
}
#define FMA2(acc, a, b)   asm("fma.rn.f32x2 %0, %1, %2, %0;" : "+l"(acc) : "l"(a), "l"(b))
#define MUL2(d, a, b)     asm("mul.rn.f32x2 %0, %1, %2;"     : "=l"(d)  : "l"(a), "l"(b))
#define ADD2(acc, a)      asm("add.rn.f32x2 %0, %0, %1;"     : "+l"(acc) : "l"(a))

// ---------------------------------------------------------------------------
// setup: blocks 0..64 -> P1^T (+C3); block 65 -> L,Q; blocks 66..321 -> W2^T
// ---------------------------------------------------------------------------
__global__ __launch_bounds__(256) void setup_kernel(const float* __restrict__ Wmod,
                                                    const float* __restrict__ bmod,
                                                    const float* __restrict__ Wg,
                                                    const float* __restrict__ adj) {
    const int tid = threadIdx.x;
    const int bid = blockIdx.x;
    if (bid >= 66) {
        // W2^T transpose + hi/lo split: 16x16 tiles of 32x32
        __shared__ float tile[32][33];
        int id = bid - 66;
        int n0 = (id & 15) * 32, k0 = (id >> 4) * 32;
        int tx = tid & 31, ty8 = tid >> 5;
        #pragma unroll
        for (int i = 0; i < 4; i++) {
            int r = ty8 + i * 8;
            tile[r][tx] = Wmod[(size_t)(k0 + r) * (2 * DIM) + DIM + n0 + tx];
        }
        __syncthreads();
        #pragma unroll
        for (int i = 0; i < 4; i++) {
            int r = ty8 + i * 8;
            float v = tile[tx][r];
            __nv_bfloat16 h = __float2bfloat16(v);
            size_t base = (size_t)(n0 + r) * KPS + (k0 + tx);
            g_Bp[base]       = h;
            g_Bp[base + 512] = __float2bfloat16(v - __bfloat162float(h));
        }
        return;
    }
    if (bid == 65) {
        __shared__ float sD[NN];
        __shared__ float sL[NN * NN];
        if (tid < NN) {
            float s = 0.f;
            #pragma unroll
            for (int m = 0; m < NN; m++) s += adj[tid * NN + m];
            sD[tid] = rsqrtf(s);
        }
        __syncthreads();
        for (int i = tid; i < NN * NN; i += 256) {
            int n = i / NN, m = i % NN;
            float v = ((n == m) ? 1.f : 0.f) - sD[n] * adj[i] * sD[m];
            sL[i] = v; g_L[i] = v;
        }
        __syncthreads();
        for (int i = tid; i < NN * NN; i += 256) {
            int n = i / NN, m = i % NN;
            float s = 0.f;
            #pragma unroll
            for (int j = 0; j < NN; j++) s += sL[n * NN + j] * sL[j * NN + m];
            g_Q[i] = 2.f * s - ((n == m) ? 1.f : 0.f);
        }
        return;
    }
    __shared__ float sWgT[9][DIM];
    const int w = tid >> 5, l = tid & 31;
    for (int i = tid; i < 9 * DIM; i += 256) {
        int k = i / (DIM * 3), r = i % (DIM * 3), c = r / 3, o = r % 3;
        sWgT[k * 3 + o][c] = Wg[i];
    }
    __syncthreads();
    int d = bid * 8 + w;
    if (d > DIM) return;
    float acc[9];
    #pragma unroll
    for (int t = 0; t < 9; t++) acc[t] = 0.f;
    #pragma unroll
    for (int j = 0; j < 4; j++) {
        int idx = j * 32 + l;
        float4 wv = (d < DIM)
            ? reinterpret_cast<const float4*>(Wmod + (size_t)d * 2 * DIM)[idx]
            : reinterpret_cast<const float4*>(bmod)[idx];
        #pragma unroll
        for (int t = 0; t < 9; t++) {
            float4 p = reinterpret_cast<const float4*>(sWgT[t])[idx];
            acc[t] += wv.x * p.x + wv.y * p.y + wv.z * p.z + wv.w * p.w;
        }
    }
    #pragma unroll
    for (int t = 0; t < 9; t++) {
        float a = acc[t];
        #pragma unroll
        for (int off = 16; off; off >>= 1) a += __shfl_xor_sync(0xffffffffu, a, off);
        if (l == 0) {
            if (d < DIM) g_P1T[t * DIM + d] = a;
            else         g_C3[t] = a;
        }
    }
}

// ---------------------------------------------------------------------------
// prep_c: fused silu(c) -> bf16 hi/lo [hi|lo] A' write  +  t3 dot products
// ---------------------------------------------------------------------------
__global__ __launch_bounds__(256) void prep_c(const float* __restrict__ cin) {
    __shared__ float sP[9][DIM];
    __shared__ float sC[9];
    const int tid = threadIdx.x, w = tid >> 5, l = tid & 31;
    for (int i = tid; i < 9 * DIM; i += 256) (&sP[0][0])[i] = g_P1T[i];
    if (tid < 9) sC[tid] = g_C3[tid];
    __syncthreads();
    const int b = blockIdx.x * 8 + w;
    float acc[9];
    #pragma unroll
    for (int t = 0; t < 9; t++) acc[t] = 0.f;
    const float4* cv = reinterpret_cast<const float4*>(cin + (size_t)b * DIM);
    __nv_bfloat16* ap = g_Ap + (size_t)b * KPS;
    #pragma unroll
    for (int j = 0; j < 4; j++) {
        int idx = j * 32 + l;
        float4 v = cv[idx];
        float s[4] = { silu_f(v.x), silu_f(v.y), silu_f(v.z), silu_f(v.w) };
        union U { __nv_bfloat16 b[4]; uint2 u; } hi, lo;
        #pragma unroll
        for (int e = 0; e < 4; e++) {
            __nv_bfloat16 h = __float2bfloat16(s[e]);
            hi.b[e] = h;
            lo.b[e] = __float2bfloat16(s[e] - __bfloat162float(h));
        }
        int kb = idx * 4;
        *reinterpret_cast<uint2*>(ap + kb)       = hi.u;
        *reinterpret_cast<uint2*>(ap + 512 + kb) = lo.u;
        #pragma unroll
        for (int t = 0; t < 9; t++) {
            float4 p = reinterpret_cast<const float4*>(sP[t])[idx];
            acc[t] += s[0] * p.x + s[1] * p.y + s[2] * p.z + s[3] * p.w;
        }
    }
    #pragma unroll
    for (int t = 0; t < 9; t++) {
        float a = acc[t];
        #pragma unroll
        for (int off = 16; off; off >>= 1) a += __shfl_xor_sync(0xffffffffu, a, off);
        if (l == 0) g_T3[(size_t)b * 9 + t] = a + sC[t];
    }
}

// ---------------------------------------------------------------------------
// scale GEMM: logical [4096,512] = A'[4096,1536] @ B'^T with segment mapping:
//   A chunks 0-7 -> hi, 8-15 -> lo, 16-23 -> hi (re-read)
//   B chunks 0-7 -> hi, 8-15 -> hi (re-read), 16-23 -> lo
// CTA 128x128, 8 warps (32x64), 4-stage cp.async, fragment double-buffering.
// ---------------------------------------------------------------------------
#define TM 128
#define TN 128
#define TK 64
#define NSTAGE 4
#define A_ST_B (TM * TK * 2)
#define B_ST_B (TN * TK * 2)
#define STAGE_B (A_ST_B + B_ST_B)
#define GSMEM (STAGE_B * NSTAGE)

__global__ __launch_bounds__(256, 1) void scale_gemm(const float* __restrict__ bmod) {
    extern __shared__ __align__(128) char sm[];
    const uint32_t sbase = smem_u32(sm);
    const int tid = threadIdx.x;
    const int wid = tid >> 5, l = tid & 31;
    const int wm = wid >> 1, wn = wid & 1;
    const int m0 = blockIdx.x * TM, n0 = blockIdx.y * TN;

    auto load_stage = [&](int st, int chunk) {
        uint32_t abase = sbase + st * STAGE_B;
        uint32_t bbase = abase + A_ST_B;
        int k0 = chunk * TK;
        int ka = (k0 >= 1024) ? k0 - 1024 : k0;        // A: [hi|lo|hi]
        int kb = (k0 >= 512)  ? k0 - 512  : k0;        // B: [hi|hi|lo]
        #pragma unroll
        for (int i = 0; i < 4; i++) {
            int id = tid + i * 256;
            int row = id >> 3, kc = id & 7;
            uint32_t dst = abase + row * 128 + ((kc ^ (row & 7)) << 4);
            cp16(dst, g_Ap + (size_t)(m0 + row) * KPS + ka + kc * 8);
        }
        #pragma unroll
        for (int i = 0; i < 4; i++) {
            int id = tid + i * 256;
            int row = id >> 3, kc = id & 7;
            uint32_t dst = bbase + row * 128 + ((kc ^ (row & 7)) << 4);
            cp16(dst, g_Bp + (size_t)(n0 + row) * KPS + kb + kc * 8);
        }
    };

    float acc[2][8][4];
    #pragma unroll
    for (int mt = 0; mt < 2; mt++)
        #pragma unroll
        for (int nt = 0; nt < 8; nt++)
            #pragma unroll
            for (int e = 0; e < 4; e++) acc[mt][nt][e] = 0.f;

    #pragma unroll
    for (int s = 0; s < 3; s++) { load_stage(s, s); CP_COMMIT(); }

    const int NCHUNK = KP / TK;            // 24
    for (int it = 0; it < NCHUNK; ++it) {
        CP_WAIT(2);
        __syncthreads();
        if (it + 3 < NCHUNK) load_stage((it + 3) & 3, it + 3);
        CP_COMMIT();
        uint32_t abase = sbase + (it & 3) * STAGE_B;
        uint32_t bbase = abase + A_ST_B;

        uint32_t a[2][2][4], b[2][4][4];
        auto load_frags = [&](int slot, int kk) {
            int kc0 = kk * 2 + (l >> 4);
            #pragma unroll
            for (int mt = 0; mt < 2; mt++) {
                int row = wm * 32 + mt * 16 + (l & 15);
                ldmx4(a[slot][mt], abase + row * 128 + ((kc0 ^ (row & 7)) << 4));
            }
            #pragma unroll
            for (int g = 0; g < 4; g++) {
                int row = wn * 64 + g * 16 + (l & 15);
                ldmx4(b[slot][g], bbase + row * 128 + ((kc0 ^ (row & 7)) << 4));
            }
        };

        load_frags(0, 0);
        #pragma unroll
        for (int kk = 0; kk < 4; kk++) {
            const int cur = kk & 1;
            if (kk < 3) load_frags(cur ^ 1, kk + 1);
            #pragma unroll
            for (int mt = 0; mt < 2; mt++)
                #pragma unroll
                for (int g = 0; g < 4; g++) {
                    uint32_t b0[2] = { b[cur][g][0], b[cur][g][2] };
                    uint32_t b1[2] = { b[cur][g][1], b[cur][g][3] };
                    mma_bf16(acc[mt][2 * g],     a[cur][mt], b0);
                    mma_bf16(acc[mt][2 * g + 1], a[cur][mt], b1);
                }
        }
    }
    CP_WAIT(0);

    const int fr = l >> 2, fc = (l & 3) * 2;
    #pragma unroll
    for (int mt = 0; mt < 2; mt++) {
        int m = m0 + wm * 32 + mt * 16 + fr;
        #pragma unroll
        for (int nt = 0; nt < 8; nt++) {
            int n = n0 + wn * 64 + nt * 8 + fc;
            float2 bv = *reinterpret_cast<const float2*>(bmod + DIM + n);
            float2 v0 = make_float2(acc[mt][nt][0] + bv.x, acc[mt][nt][1] + bv.y);
            float2 v1 = make_float2(acc[mt][nt][2] + bv.x, acc[mt][nt][3] + bv.y);
            *reinterpret_cast<float2*>(g_scale + (size_t)m * DIM + n) = v0;
            *reinterpret_cast<float2*>(g_scale + (size_t)(m + 8) * DIM + n) = v1;
        }
    }
}

// ---------------------------------------------------------------------------
// final: single-pass u-trick + deferred combine (R11, measured best).
// ---------------------------------------------------------------------------
#define BPB 4
#define XROWS 18
#define XF (XROWS * DIM)              // 9216 floats per buffer
#define SM_WG 0
#define SM_L  (SM_WG + 9 * DIM)
#define SM_Q  (SM_L + NN * NN)
#define SM_T3 (SM_Q + NN * NN)
#define SM_D  (SM_T3 + 4 * 9)
#define SM_Y  (SM_D + 4 * 18 * 11 * 2)
#define SM_X  7424
#define SM_SC (SM_X + 2 * XF)
#define SM_F_TOT (SM_SC + 2 * DIM)
#define GSMEM_F (SM_F_TOT * 4)

__global__ __launch_bounds__(192, 2) void final_kernel(const float* __restrict__ x,
                                                       const float* __restrict__ Wg,
                                                       const float* __restrict__ bg,
                                                       float* __restrict__ out) {
    extern __shared__ __align__(16) float sf[];
    const uint32_t sbase = smem_u32(sf);
    const int tid = threadIdx.x;
    const int w = tid >> 5;
    const int l = tid & 31;

    auto stage = [&](int bb, int buf) {
        const int b = blockIdx.x * BPB + bb;
        const float* xp = x + (size_t)b * (NN * DIM);
        uint32_t dstx = sbase + (SM_X + buf * XF) * 4;
        #pragma unroll
        for (int i = 0; i < 12; i++) {
            int id = tid + i * 192;
            if (id < (NN * DIM) / 4) cp16(dstx + id * 16, xp + id * 4);
        }
        if (tid < DIM / 4)
            cp16(sbase + (SM_SC + buf * DIM) * 4 + tid * 16,
                 g_scale + (size_t)b * DIM + tid * 4);
    };

    stage(0, 0); CP_COMMIT();

    for (int i = tid; i < 9 * DIM; i += 192) {
        int k = i / (DIM * 3), r = i % (DIM * 3), c = r / 3, o = r % 3;
        sf[SM_WG + (k * 3 + o) * DIM + c] = Wg[i];
    }
    for (int i = tid; i < NN * NN; i += 192) {
        sf[SM_L + i] = g_L[i];
        sf[SM_Q + i] = g_Q[i];
    }
    for (int i = tid; i < DIM; i += 192) {
        sf[SM_X + NN * DIM + i]      = 1.f;
        sf[SM_X + XF + NN * DIM + i] = 1.f;
    }

    for (int bb = 0; bb < BPB; ++bb) {
        const int b = blockIdx.x * BPB + bb;
        const int buf = bb & 1;
        CP_WAIT(0);
        __syncthreads();
        if (bb + 1 < BPB) { stage(bb + 1, buf ^ 1); CP_COMMIT(); }
        if (tid < 9) sf[SM_T3 + bb * 9 + tid] = g_T3[(size_t)b * 9 + tid];

        const float* sx  = sf + SM_X + buf * XF;
        const float* ssc = sf + SM_SC + buf * DIM;

        u64 acc2[3][11];
        #pragma unroll
        for (int r = 0; r < 3; r++)
            #pragma unroll
            for (int t = 0; t < 11; t++) acc2[r][t] = 0ull;

        #pragma unroll
        for (int j = 0; j < 4; j++) {
            const int idx = j * 32 + l;
            float4 sc = reinterpret_cast<const float4*>(ssc)[idx];
            u64 g01 = pack2(sc.x + 1.f, sc.y + 1.f);
            u64 g23 = pack2(sc.z + 1.f, sc.w + 1.f);
            u64 wv01[9], wv23[9];
            #pragma unroll
            for (int t = 0; t < 9; t++) {
                float4 wv = reinterpret_cast<const float4*>(sf + SM_WG + t * DIM)[idx];
                wv01[t] = pack2(wv.x, wv.y);
                wv23[t] = pack2(wv.z, wv.w);
            }
            #pragma unroll
            for (int r = 0; r < 3; r++) {
                const int n = w * 3 + r;
                float4 v = reinterpret_cast<const float4*>(sx + n * DIM)[idx];
                u64 v01 = pack2(v.x, v.y), v23 = pack2(v.z, v.w);
                u64 xm01, xm23;
                MUL2(xm01, v01, g01);
                MUL2(xm23, v23, g23);
                ADD2(acc2[r][9], v01); ADD2(acc2[r][9], v23);
                FMA2(acc2[r][10], v01, v01); FMA2(acc2[r][10], v23, v23);
                #pragma unroll
                for (int t = 0; t < 9; t++) {
                    FMA2(acc2[r][t], xm01, wv01[t]);
                    FMA2(acc2[r][t], xm23, wv23[t]);
                }
            }
        }

        #pragma unroll
        for (int r = 0; r < 3; r++) {
            const int n = w * 3 + r;
            #pragma unroll
            for (int t = 0; t < 11; t++) {
                F2 u; u.u = acc2[r][t];
                float a = u.f.x + u.f.y;
                a += __shfl_xor_sync(0xffffffffu, a, 16);
                a += __shfl_xor_sync(0xffffffffu, a, 8);
                a += __shfl_xor_sync(0xffffffffu, a, 4);
                a += __shfl_xor_sync(0xffffffffu, a, 2);
                if (l < 2)
                    sf[SM_D + (((bb * 18 + n) * 11) + t) * 2 + l] = a;
            }
        }
    }
    __syncthreads();

    for (int i = tid; i < 4 * 153; i += 192) {
        int b4 = i / 153, r = i % 153;
        int k = r / 51, rr = r % 51, n = rr / 3, o = rr % 3;
        int t = k * 3 + o;
        const float* dbase = sf + SM_D + ((b4 * 18 + n) * 11) * 2;
        const float* ubase = sf + SM_D + ((b4 * 18 + 17) * 11) * 2;
        float d = dbase[t * 2] + dbase[t * 2 + 1];
        float u = ubase[t * 2] + ubase[t * 2 + 1];
        float s  = dbase[9 * 2]  + dbase[9 * 2 + 1];
        float s2 = dbase[10 * 2] + dbase[10 * 2 + 1];
        float mu = s * (1.f / DIM);
        float var = s2 * (1.f / DIM) - mu * mu;
        float rstd = rsqrtf(var + 1e-6f);
        sf[SM_Y + ((b4 * 3 + k) * NN + n) * OUTC + o] = rstd * (d - mu * u);
    }
    __syncthreads();

    for (int i = tid; i < 4 * NN * OUTC; i += 192) {
        int b4 = i / (NN * OUTC), r = i % (NN * OUTC);
        int n = r / OUTC, o = r % OUTC;
        const int b = blockIdx.x * BPB + b4;
        const float* t3 = sf + SM_T3 + b4 * 9;
        const float* y0 = sf + SM_Y + (b4 * 3 + 0) * NN * OUTC;
        const float* y1 = sf + SM_Y + (b4 * 3 + 1) * NN * OUTC;
        const float* y2 = sf + SM_Y + (b4 * 3 + 2) * NN * OUTC;
        float t31 = t3[3 + o], t32 = t3[6 + o];
        float res = y0[n * OUTC + o] + t3[o] + bg[o];
        #pragma unroll
        for (int m = 0; m < NN; m++)
            res += sf[SM_L + n * NN + m] * (y1[m * OUTC + o] + t31)
                 + sf[SM_Q + n * NN + m] * (y2[m * OUTC + o] + t32);
        out[((size_t)b * NN + n) * OUTC + o] = res;
    }
}

// ---------------------------------------------------------------------------
extern "C" void kernel_launch(void* const* d_in, const int* in_sizes, int n_in,
                              void* d_out, int out_size) {
    const float* x     = (const float*)d_in[0];  // [4096,17,512]
    const float* adj   = (const float*)d_in[1];  // [17,17]
    const float* c     = (const float*)d_in[2];  // [4096,1,512]
    const float* W_mod = (const float*)d_in[3];  // [512,1024]
    const float* b_mod = (const float*)d_in[4];  // [1024]
    const float* Wg    = (const float*)d_in[5];  // [3,512,3]
    const float* bg    = (const float*)d_in[6];  // [3]
    float* out = (float*)d_out;                  // [4096,17,3] f32

    cudaFuncSetAttribute(scale_gemm, cudaFuncAttributeMaxDynamicSharedMemorySize, GSMEM);
    cudaFuncSetAttribute(final_kernel, cudaFuncAttributeMaxDynamicSharedMemorySize, GSMEM_F);

    setup_kernel<<<322, 256>>>(W_mod, b_mod, Wg, adj);
    prep_c<<<BATCH / 8, 256>>>(c);
    scale_gemm<<<dim3(BATCH / TM, DIM / TN), 256, GSMEM>>>(b_mod);
    final_kernel<<<BATCH / BPB, 192, GSMEM_F>>>(x, Wg, bg, out);
}